// round 1
// baseline (speedup 1.0000x reference)
#include <cuda_runtime.h>
#include <cstdint>

#define HH   1024
#define BB   64
#define SS   256
#define DD   512
#define G4H  4096

// ---------------- scratch (device globals: allocation-free) ----------------
__device__ float d_gx0[(size_t)SS * BB * G4H];    // [S,B,4H] layer0 input proj
__device__ float d_gx1[(size_t)SS * BB * G4H];    // [S,B,4H] layer1 input proj
__device__ float d_h1buf[(size_t)SS * BB * HH];   // [S,B,H]  layer0 outputs
__device__ float d_hbuf[2][BB * HH];              // double-buffered h
__device__ unsigned g_cnt;
__device__ volatile unsigned g_gen;

// ---------------- helpers ----------------
__device__ __forceinline__ unsigned f2tf(float x) {
    unsigned r;
    asm("cvt.rna.tf32.f32 %0, %1;" : "=r"(r) : "f"(x));
    return r;
}

__device__ __forceinline__ void st4(unsigned* p, float4 v) {
    p[0] = f2tf(v.x); p[1] = f2tf(v.y); p[2] = f2tf(v.z); p[3] = f2tf(v.w);
}

__device__ __forceinline__ void mma8(float d[4], const unsigned a[4], const unsigned b[2]) {
    asm volatile(
        "mma.sync.aligned.m16n8k8.row.col.f32.tf32.tf32.f32 "
        "{%0,%1,%2,%3},{%4,%5,%6,%7},{%8,%9},{%0,%1,%2,%3};\n"
        : "+f"(d[0]), "+f"(d[1]), "+f"(d[2]), "+f"(d[3])
        : "r"(a[0]), "r"(a[1]), "r"(a[2]), "r"(a[3]), "r"(b[0]), "r"(b[1]));
}

// warp computes a 32x32 tile: 2 m16 x 4 n8, over BK=16 (two k8 halves)
__device__ __forceinline__ void wtile_mma(float acc[2][4][4],
                                          const unsigned (*As)[20],
                                          const unsigned (*Bs)[20],
                                          int mb, int nb, int g4, int t4) {
#pragma unroll
    for (int kk = 0; kk < 2; kk++) {
        const int k8 = kk * 8;
        unsigned af[2][4], bf[4][2];
#pragma unroll
        for (int im = 0; im < 2; im++) {
            const int r = mb + im * 16;
            af[im][0] = As[r + g4][k8 + t4];
            af[im][1] = As[r + 8 + g4][k8 + t4];
            af[im][2] = As[r + g4][k8 + 4 + t4];
            af[im][3] = As[r + 8 + g4][k8 + 4 + t4];
        }
#pragma unroll
        for (int in = 0; in < 4; in++) {
            const int c = nb + in * 8;
            bf[in][0] = Bs[c + g4][k8 + t4];
            bf[in][1] = Bs[c + g4][k8 + 4 + t4];
        }
#pragma unroll
        for (int im = 0; im < 2; im++)
#pragma unroll
            for (int in = 0; in < 4; in++)
                mma8(acc[im][in], af[im], bf[in]);
    }
}

__device__ __forceinline__ void grid_barrier(unsigned nct) {
    __threadfence();
    __syncthreads();
    if (threadIdx.x == 0) {
        const unsigned g = g_gen;
        if (atomicAdd(&g_cnt, 1u) == nct - 1u) {
            g_cnt = 0u;
            __threadfence();
            g_gen = g + 1u;
        } else {
            while (g_gen == g) __nanosleep(32);
            __threadfence();
        }
    }
    __syncthreads();
}

// ---------------- input-projection GEMM ----------------
// C[M,4096] = A[M,K] @ W[4096,K]^T + (bias1 + bias2)
// REMAP: row m=(b*S+s) written to gx[(s*B+b)]
template <bool REMAP>
__global__ __launch_bounds__(256) void proj_kernel(
    const float* __restrict__ A, const float* __restrict__ W,
    const float* __restrict__ bias1, const float* __restrict__ bias2,
    float* __restrict__ C, int K) {
    __shared__ unsigned As[2][64][20];
    __shared__ unsigned Bs[2][128][20];

    const int tid = threadIdx.x;
    const int lane = tid & 31, warp = tid >> 5;
    const int wm = warp >> 2, wn = warp & 3;   // 2 x 4 warps
    const int g4 = lane >> 2, t4 = lane & 3;
    const int m0 = blockIdx.y * 64;
    const int n0 = blockIdx.x * 128;

    float acc[2][4][4];
#pragma unroll
    for (int a = 0; a < 2; a++)
#pragma unroll
        for (int b = 0; b < 4; b++)
#pragma unroll
            for (int c = 0; c < 4; c++) acc[a][b][c] = 0.f;

    const int ar = tid >> 2;
    const int ac = (tid & 3) << 2;
    const float* Ap  = A + (size_t)(m0 + ar) * K + ac;
    const float* Bp0 = W + (size_t)(n0 + ar) * K + ac;
    const float* Bp1 = W + (size_t)(n0 + ar + 64) * K + ac;
    const int KT = K >> 4;

    float4 av  = *(const float4*)Ap;
    float4 bv0 = *(const float4*)Bp0;
    float4 bv1 = *(const float4*)Bp1;
    st4(&As[0][ar][ac], av);
    st4(&Bs[0][ar][ac], bv0);
    st4(&Bs[0][ar + 64][ac], bv1);
    __syncthreads();

    int buf = 0;
    for (int kt = 0; kt < KT; kt++) {
        const int kn = (kt + 1) << 4;
        if (kt + 1 < KT) {
            av  = *(const float4*)(Ap + kn);
            bv0 = *(const float4*)(Bp0 + kn);
            bv1 = *(const float4*)(Bp1 + kn);
        }
        wtile_mma(acc, As[buf], Bs[buf], wm * 32, wn * 32, g4, t4);
        if (kt + 1 < KT) {
            st4(&As[buf ^ 1][ar][ac], av);
            st4(&Bs[buf ^ 1][ar][ac], bv0);
            st4(&Bs[buf ^ 1][ar + 64][ac], bv1);
        }
        __syncthreads();
        buf ^= 1;
    }

#pragma unroll
    for (int im = 0; im < 2; im++) {
#pragma unroll
        for (int in = 0; in < 4; in++) {
            const int col = n0 + wn * 32 + in * 8 + (t4 << 1);
            const float bb0 = bias1[col] + bias2[col];
            const float bb1 = bias1[col + 1] + bias2[col + 1];
            const int r0 = m0 + wm * 32 + im * 16 + g4;
            const int r1 = r0 + 8;
            size_t o0, o1;
            if (REMAP) {
                o0 = ((size_t)((r0 & (SS - 1)) * BB + (r0 >> 8))) * G4H + col;
                o1 = ((size_t)((r1 & (SS - 1)) * BB + (r1 >> 8))) * G4H + col;
            } else {
                o0 = (size_t)r0 * G4H + col;
                o1 = (size_t)r1 * G4H + col;
            }
            *(float2*)(C + o0) = make_float2(acc[im][in][0] + bb0, acc[im][in][1] + bb1);
            *(float2*)(C + o1) = make_float2(acc[im][in][2] + bb0, acc[im][in][3] + bb1);
        }
    }
}

// ---------------- persistent recurrent kernel ----------------
// 64 CTAs; CTA c owns hidden units j in [c*16, c*16+16) across all 4 gates.
// Per step: g = gx[t] + h_prev @ Whh^T (gate-gathered N=64 tile), then fused
// LSTM cell update. c-state lives in smem. Grid barrier between steps.
template <bool FINAL>
__global__ __launch_bounds__(128) void rec_kernel(
    const float* __restrict__ gx, const float* __restrict__ Whh,
    float* __restrict__ out) {
    __shared__ unsigned As[2][64][20];
    __shared__ unsigned Bs[2][64][20];
    __shared__ float gsm[64][66];
    __shared__ float csm[64][16];

    const int tid = threadIdx.x;
    const int lane = tid & 31, warp = tid >> 5;
    const int wm = warp >> 1, wn = warp & 1;   // 2 x 2 warps
    const int g4 = lane >> 2, t4 = lane & 3;
    const int jb = blockIdx.x << 4;
    const unsigned nct = gridDim.x;

    // zero h[0] (our columns) and c state
#pragma unroll
    for (int it = 0; it < 8; it++) {
        const int idx = tid + it * 128;
        const int b = idx >> 4, jj = idx & 15;
        d_hbuf[0][b * HH + jb + jj] = 0.f;
        csm[b][jj] = 0.f;
    }
    grid_barrier(nct);

    const int r0 = tid >> 2;         // 0..31
    const int cq = (tid & 3) << 2;
    const int v0 = r0, v1 = r0 + 32; // virtual cols: gate = v>>4, j = jb + (v&15)
    const float* wp0 = Whh + (size_t)((v0 >> 4) * HH + jb + (v0 & 15)) * HH + cq;
    const float* wp1 = Whh + (size_t)((v1 >> 4) * HH + jb + (v1 & 15)) * HH + cq;

    for (int t = 0; t < SS; t++) {
        const float* hprev = d_hbuf[t & 1];
        float* hnext = d_hbuf[(t + 1) & 1];

        float acc[2][4][4];
#pragma unroll
        for (int a = 0; a < 2; a++)
#pragma unroll
            for (int b = 0; b < 4; b++)
#pragma unroll
                for (int c = 0; c < 4; c++) acc[a][b][c] = 0.f;

        const float* ap0 = hprev + (size_t)v0 * HH + cq;
        const float* ap1 = hprev + (size_t)v1 * HH + cq;

        float4 av0 = __ldcg((const float4*)ap0);
        float4 av1 = __ldcg((const float4*)ap1);
        float4 bv0 = *(const float4*)wp0;
        float4 bv1 = *(const float4*)wp1;
        st4(&As[0][v0][cq], av0); st4(&As[0][v1][cq], av1);
        st4(&Bs[0][v0][cq], bv0); st4(&Bs[0][v1][cq], bv1);
        __syncthreads();

        int buf = 0;
        for (int kt = 0; kt < 64; kt++) {
            const int kn = (kt + 1) << 4;
            if (kt < 63) {
                av0 = __ldcg((const float4*)(ap0 + kn));
                av1 = __ldcg((const float4*)(ap1 + kn));
                bv0 = *(const float4*)(wp0 + kn);
                bv1 = *(const float4*)(wp1 + kn);
            }
            wtile_mma(acc, As[buf], Bs[buf], wm * 32, wn * 32, g4, t4);
            if (kt < 63) {
                st4(&As[buf ^ 1][v0][cq], av0); st4(&As[buf ^ 1][v1][cq], av1);
                st4(&Bs[buf ^ 1][v0][cq], bv0); st4(&Bs[buf ^ 1][v1][cq], bv1);
            }
            __syncthreads();
            buf ^= 1;
        }

        // dump accumulators to smem for the gate exchange
#pragma unroll
        for (int im = 0; im < 2; im++) {
#pragma unroll
            for (int in = 0; in < 4; in++) {
                const int cc = wn * 32 + in * 8 + (t4 << 1);
                const int rr = wm * 32 + im * 16 + g4;
                *(float2*)(&gsm[rr][cc])     = make_float2(acc[im][in][0], acc[im][in][1]);
                *(float2*)(&gsm[rr + 8][cc]) = make_float2(acc[im][in][2], acc[im][in][3]);
            }
        }
        __syncthreads();

        // fused LSTM cell update (each (b,jj) handled by a fixed thread)
        const float* gxt = gx + (size_t)t * (BB * G4H);
#pragma unroll
        for (int it = 0; it < 8; it++) {
            const int idx = tid + it * 128;
            const int b = idx >> 4, jj = idx & 15;
            const float* gp = gxt + (size_t)b * G4H + jb + jj;
            const float gi = gsm[b][jj]      + gp[0];
            const float gf = gsm[b][16 + jj] + gp[HH];
            const float gg = gsm[b][32 + jj] + gp[2 * HH];
            const float go = gsm[b][48 + jj] + gp[3 * HH];
            const float iv = 1.f / (1.f + expf(-gi));
            const float fv = 1.f / (1.f + expf(-gf));
            const float gv = tanhf(gg);
            const float ov = 1.f / (1.f + expf(-go));
            const float cv = fv * csm[b][jj] + iv * gv;
            csm[b][jj] = cv;
            const float hv = ov * tanhf(cv);
            hnext[b * HH + jb + jj] = hv;
            if (FINAL) {
                const float rv = hv > 0.f ? hv : 0.f;
                out[(size_t)b * (SS * HH) + t * HH + jb + jj] = 1.f / (1.f + expf(-rv));
            } else {
                out[((size_t)t * BB + b) * HH + jb + jj] = hv;
            }
        }
        grid_barrier(nct);
    }
}

// ---------------- launch ----------------
extern "C" void kernel_launch(void* const* d_in, const int* in_sizes, int n_in,
                              void* d_out, int out_size) {
    const float* x    = (const float*)d_in[0];
    const float* Wih0 = (const float*)d_in[1];
    const float* Whh0 = (const float*)d_in[2];
    const float* bih0 = (const float*)d_in[3];
    const float* bhh0 = (const float*)d_in[4];
    const float* Wih1 = (const float*)d_in[5];
    const float* Whh1 = (const float*)d_in[6];
    const float* bih1 = (const float*)d_in[7];
    const float* bhh1 = (const float*)d_in[8];
    float* out = (float*)d_out;

    float *gx0, *gx1, *h1;
    cudaGetSymbolAddress((void**)&gx0, d_gx0);
    cudaGetSymbolAddress((void**)&gx1, d_gx1);
    cudaGetSymbolAddress((void**)&h1,  d_h1buf);

    dim3 gridP(G4H / 128, (BB * SS) / 64);   // (32, 256)

    proj_kernel<true><<<gridP, 256>>>(x, Wih0, bih0, bhh0, gx0, DD);
    rec_kernel<false><<<64, 128>>>(gx0, Whh0, h1);
    proj_kernel<false><<<gridP, 256>>>(h1, Wih1, bih1, bhh1, gx1, HH);
    rec_kernel<true><<<64, 128>>>(gx1, Whh1, out);
}

// round 2
// speedup vs baseline: 2.3631x; 2.3631x over previous
#include <cuda_runtime.h>
#include <cstdint>

#define HH   1024
#define BB   64
#define SS   256
#define DD   512
#define G4H  4096

// ---------------- scratch (device globals: allocation-free) ----------------
__device__ float d_gx0[(size_t)SS * BB * G4H];    // [S,B,4H] layer0 input proj
__device__ float d_gx1[(size_t)SS * BB * G4H];    // [S,B,4H] layer1 input proj
__device__ float d_h1buf[(size_t)SS * BB * HH];   // [S,B,H]  layer0 outputs
__device__ float d_hbuf[2][BB * HH];              // double-buffered h (tf32-rounded)
__device__ unsigned g_cnt;
__device__ volatile unsigned g_gen;

// ---------------- helpers ----------------
__device__ __forceinline__ unsigned f2tf(float x) {
    unsigned r;
    asm("cvt.rna.tf32.f32 %0, %1;" : "=r"(r) : "f"(x));
    return r;
}

__device__ __forceinline__ void st4(unsigned* p, float4 v) {
    p[0] = f2tf(v.x); p[1] = f2tf(v.y); p[2] = f2tf(v.z); p[3] = f2tf(v.w);
}

__device__ __forceinline__ void mma8(float d[4], const unsigned a[4], const unsigned b[2]) {
    asm volatile(
        "mma.sync.aligned.m16n8k8.row.col.f32.tf32.tf32.f32 "
        "{%0,%1,%2,%3},{%4,%5,%6,%7},{%8,%9},{%0,%1,%2,%3};\n"
        : "+f"(d[0]), "+f"(d[1]), "+f"(d[2]), "+f"(d[3])
        : "r"(a[0]), "r"(a[1]), "r"(a[2]), "r"(a[3]), "r"(b[0]), "r"(b[1]));
}

__device__ __forceinline__ void grid_barrier(unsigned nct) {
    __threadfence();
    __syncthreads();
    if (threadIdx.x == 0) {
        const unsigned g = g_gen;
        if (atomicAdd(&g_cnt, 1u) == nct - 1u) {
            g_cnt = 0u;
            __threadfence();
            g_gen = g + 1u;
        } else {
            while (g_gen == g) __nanosleep(32);
            __threadfence();
        }
    }
    __syncthreads();
}

// ---------------- input-projection GEMM (unchanged from R1) ----------------
template <bool REMAP>
__global__ __launch_bounds__(256) void proj_kernel(
    const float* __restrict__ A, const float* __restrict__ W,
    const float* __restrict__ bias1, const float* __restrict__ bias2,
    float* __restrict__ C, int K) {
    __shared__ unsigned As[2][64][20];
    __shared__ unsigned Bs[2][128][20];

    const int tid = threadIdx.x;
    const int lane = tid & 31, warp = tid >> 5;
    const int wm = warp >> 2, wn = warp & 3;
    const int g4 = lane >> 2, t4 = lane & 3;
    const int m0 = blockIdx.y * 64;
    const int n0 = blockIdx.x * 128;

    float acc[2][4][4];
#pragma unroll
    for (int a = 0; a < 2; a++)
#pragma unroll
        for (int b = 0; b < 4; b++)
#pragma unroll
            for (int c = 0; c < 4; c++) acc[a][b][c] = 0.f;

    const int ar = tid >> 2;
    const int ac = (tid & 3) << 2;
    const float* Ap  = A + (size_t)(m0 + ar) * K + ac;
    const float* Bp0 = W + (size_t)(n0 + ar) * K + ac;
    const float* Bp1 = W + (size_t)(n0 + ar + 64) * K + ac;
    const int KT = K >> 4;

    float4 av  = *(const float4*)Ap;
    float4 bv0 = *(const float4*)Bp0;
    float4 bv1 = *(const float4*)Bp1;
    st4(&As[0][ar][ac], av);
    st4(&Bs[0][ar][ac], bv0);
    st4(&Bs[0][ar + 64][ac], bv1);
    __syncthreads();

    int buf = 0;
    for (int kt = 0; kt < KT; kt++) {
        const int kn = (kt + 1) << 4;
        if (kt + 1 < KT) {
            av  = *(const float4*)(Ap + kn);
            bv0 = *(const float4*)(Bp0 + kn);
            bv1 = *(const float4*)(Bp1 + kn);
        }
        // warp 32x32 tile over BK=16
#pragma unroll
        for (int kk = 0; kk < 2; kk++) {
            const int k8 = kk * 8;
            unsigned af[2][4], bf[4][2];
#pragma unroll
            for (int im = 0; im < 2; im++) {
                const int r = wm * 32 + im * 16;
                af[im][0] = As[buf][r + g4][k8 + t4];
                af[im][1] = As[buf][r + 8 + g4][k8 + t4];
                af[im][2] = As[buf][r + g4][k8 + 4 + t4];
                af[im][3] = As[buf][r + 8 + g4][k8 + 4 + t4];
            }
#pragma unroll
            for (int in = 0; in < 4; in++) {
                const int c = wn * 32 + in * 8;
                bf[in][0] = Bs[buf][c + g4][k8 + t4];
                bf[in][1] = Bs[buf][c + g4][k8 + 4 + t4];
            }
#pragma unroll
            for (int im = 0; im < 2; im++)
#pragma unroll
                for (int in = 0; in < 4; in++)
                    mma8(acc[im][in], af[im], bf[in]);
        }
        if (kt + 1 < KT) {
            st4(&As[buf ^ 1][ar][ac], av);
            st4(&Bs[buf ^ 1][ar][ac], bv0);
            st4(&Bs[buf ^ 1][ar + 64][ac], bv1);
        }
        __syncthreads();
        buf ^= 1;
    }

#pragma unroll
    for (int im = 0; im < 2; im++) {
#pragma unroll
        for (int in = 0; in < 4; in++) {
            const int col = n0 + wn * 32 + in * 8 + (t4 << 1);
            const float bb0 = bias1[col] + bias2[col];
            const float bb1 = bias1[col + 1] + bias2[col + 1];
            const int r0 = m0 + wm * 32 + im * 16 + g4;
            const int r1 = r0 + 8;
            size_t o0, o1;
            if (REMAP) {
                o0 = ((size_t)((r0 & (SS - 1)) * BB + (r0 >> 8))) * G4H + col;
                o1 = ((size_t)((r1 & (SS - 1)) * BB + (r1 >> 8))) * G4H + col;
            } else {
                o0 = (size_t)r0 * G4H + col;
                o1 = (size_t)r1 * G4H + col;
            }
            *(float2*)(C + o0) = make_float2(acc[im][in][0] + bb0, acc[im][in][1] + bb1);
            *(float2*)(C + o1) = make_float2(acc[im][in][2] + bb0, acc[im][in][3] + bb1);
        }
    }
}

// ---------------- persistent recurrent kernel v2 ----------------
// 128 CTAs x 256 threads. CTA c owns 8 hidden units (jb=c*8) x 4 gates = 32
// gate-gathered columns. W_hh slab [32 x 1024] lives in smem (tf32) for the
// whole kernel. Per step: h (tf32, global) streamed in 8 K-chunks of 128 via
// cp.async double buffer; 8 warps = 2(M) x 2(N) x 2(K-split); partials
// reduced through smem; fused cell update; grid barrier.
// smem (floats): Ws[32][1028] | As[2][64][132] | gsm[2][64][34] | csm[512]
#define WS_STRIDE 1028
#define AS_STRIDE 132
#define AS_BUF    (64 * AS_STRIDE)
#define OFF_AS    (32 * WS_STRIDE)
#define OFF_GSM   (OFF_AS + 2 * AS_BUF)
#define GSM_BUF   (64 * 34)
#define OFF_CSM   (OFF_GSM + 2 * GSM_BUF)
#define SMEM_FLOATS (OFF_CSM + 512)
#define REC_SMEM_BYTES (SMEM_FLOATS * 4)

__device__ __forceinline__ void prefetch_h(const float* hrow0, int chunk,
                                           float* dst, int tid) {
#pragma unroll
    for (int it = 0; it < 8; it++) {
        const int s = tid + it * 256;
        const int row = s >> 5;
        const int c4 = (s & 31) << 2;
        const float* src = hrow0 + (size_t)row * HH + chunk * 128 + c4;
        unsigned d = (unsigned)__cvta_generic_to_shared(dst + row * AS_STRIDE + c4);
        asm volatile("cp.async.cg.shared.global [%0], [%1], 16;\n" :: "r"(d), "l"(src));
    }
    asm volatile("cp.async.commit_group;\n");
}

template <bool FINAL>
__global__ __launch_bounds__(256) void rec_kernel(
    const float* __restrict__ gx, const float* __restrict__ Whh,
    float* __restrict__ out) {
    extern __shared__ float sm[];
    float* Ws  = sm;
    float* Asm = sm + OFF_AS;
    float* gsm = sm + OFF_GSM;
    float* csm = sm + OFF_CSM;

    const int tid = threadIdx.x;
    const int lane = tid & 31, warp = tid >> 5;
    const int wk = warp >> 2;            // K-split half
    const int wm = (warp >> 1) & 1;      // M half (32 rows)
    const int wn = warp & 1;             // N half (16 cols)
    const int g4 = lane >> 2, t4 = lane & 3;
    const int jb = blockIdx.x << 3;      // 8 hidden units per CTA
    const unsigned nct = gridDim.x;

    // --- one-time: W slab into smem (tf32), zero h[0] slice + c state ---
    for (int idx = tid; idx < 32 * 1024; idx += 256) {
        const int v = idx >> 10, k = idx & 1023;
        const int grow = (v >> 3) * HH + jb + (v & 7);
        Ws[v * WS_STRIDE + k] = __uint_as_float(f2tf(Whh[(size_t)grow * HH + k]));
    }
    for (int idx = tid; idx < 512; idx += 256) {
        const int b = idx >> 3, u = idx & 7;
        d_hbuf[0][b * HH + jb + u] = 0.f;
        csm[idx] = 0.f;
    }
    grid_barrier(nct);

    const int cbase = tid >> 2;          // batch for cell update (0..63)
    const int u0 = (tid & 3) << 1;       // unit pair

    for (int t = 0; t < SS; t++) {
        const float* hprev = d_hbuf[t & 1];
        float* hnext = d_hbuf[(t + 1) & 1];

        // hoist gx loads (land during GEMM)
        const float* gp = gx + (size_t)t * (BB * G4H) + (size_t)cbase * G4H + jb + u0;
        const float2 gxi = *(const float2*)(gp);
        const float2 gxf = *(const float2*)(gp + HH);
        const float2 gxg = *(const float2*)(gp + 2 * HH);
        const float2 gxo = *(const float2*)(gp + 3 * HH);

        float acc[2][2][4];
#pragma unroll
        for (int a = 0; a < 2; a++)
#pragma unroll
            for (int b = 0; b < 2; b++)
#pragma unroll
                for (int c = 0; c < 4; c++) acc[a][b][c] = 0.f;

        prefetch_h(hprev, 0, Asm, tid);
        int buf = 0;
#pragma unroll 1
        for (int ci = 0; ci < 8; ci++) {
            asm volatile("cp.async.wait_group 0;\n");
            __syncthreads();
            if (ci < 7) prefetch_h(hprev, ci + 1, Asm + (buf ^ 1) * AS_BUF, tid);
            const float* Ab = Asm + buf * AS_BUF;
#pragma unroll
            for (int kk = 0; kk < 8; kk++) {
                const int ks = wk * 64 + kk * 8;      // within chunk
                const int kw = ci * 128 + ks;          // within Ws row
                unsigned af[2][4], bf[2][2];
#pragma unroll
                for (int im = 0; im < 2; im++) {
                    const int r = wm * 32 + im * 16;
                    af[im][0] = __float_as_uint(Ab[(r + g4) * AS_STRIDE + ks + t4]);
                    af[im][1] = __float_as_uint(Ab[(r + 8 + g4) * AS_STRIDE + ks + t4]);
                    af[im][2] = __float_as_uint(Ab[(r + g4) * AS_STRIDE + ks + 4 + t4]);
                    af[im][3] = __float_as_uint(Ab[(r + 8 + g4) * AS_STRIDE + ks + 4 + t4]);
                }
#pragma unroll
                for (int in = 0; in < 2; in++) {
                    const int c = wn * 16 + in * 8;
                    bf[in][0] = __float_as_uint(Ws[(c + g4) * WS_STRIDE + kw + t4]);
                    bf[in][1] = __float_as_uint(Ws[(c + g4) * WS_STRIDE + kw + 4 + t4]);
                }
#pragma unroll
                for (int im = 0; im < 2; im++)
#pragma unroll
                    for (int in = 0; in < 2; in++)
                        mma8(acc[im][in], af[im], bf[in]);
            }
            buf ^= 1;
        }

        // dump partials: gsm[wk][row][col]
#pragma unroll
        for (int im = 0; im < 2; im++) {
#pragma unroll
            for (int in = 0; in < 2; in++) {
                const int row = wm * 32 + im * 16 + g4;
                const int col = wn * 16 + in * 8 + (t4 << 1);
                float* gb = gsm + wk * GSM_BUF;
                *(float2*)(gb + row * 34 + col) =
                    make_float2(acc[im][in][0], acc[im][in][1]);
                *(float2*)(gb + (row + 8) * 34 + col) =
                    make_float2(acc[im][in][2], acc[im][in][3]);
            }
        }
        __syncthreads();

        // fused cell update: thread -> batch=cbase, units u0,u0+1
        {
            const float* g0 = gsm + cbase * 34;
            const float* g1 = gsm + GSM_BUF + cbase * 34;
            const float gi0 = g0[u0]      + g1[u0]      + gxi.x;
            const float gi1 = g0[u0 + 1]  + g1[u0 + 1]  + gxi.y;
            const float gf0 = g0[8 + u0]  + g1[8 + u0]  + gxf.x;
            const float gf1 = g0[9 + u0]  + g1[9 + u0]  + gxf.y;
            const float gg0 = g0[16 + u0] + g1[16 + u0] + gxg.x;
            const float gg1 = g0[17 + u0] + g1[17 + u0] + gxg.y;
            const float go0 = g0[24 + u0] + g1[24 + u0] + gxo.x;
            const float go1 = g0[25 + u0] + g1[25 + u0] + gxo.y;

            const float i0 = 1.f / (1.f + expf(-gi0));
            const float i1 = 1.f / (1.f + expf(-gi1));
            const float f0 = 1.f / (1.f + expf(-gf0));
            const float f1 = 1.f / (1.f + expf(-gf1));
            const float z0 = tanhf(gg0);
            const float z1 = tanhf(gg1);
            const float o0 = 1.f / (1.f + expf(-go0));
            const float o1 = 1.f / (1.f + expf(-go1));

            const int ce = cbase * 8 + u0;
            const float c0 = f0 * csm[ce] + i0 * z0;
            const float c1 = f1 * csm[ce + 1] + i1 * z1;
            csm[ce] = c0;
            csm[ce + 1] = c1;
            const float h0 = o0 * tanhf(c0);
            const float h1 = o1 * tanhf(c1);

            *(float2*)(hnext + cbase * HH + jb + u0) =
                make_float2(__uint_as_float(f2tf(h0)), __uint_as_float(f2tf(h1)));

            if (FINAL) {
                const float r0 = h0 > 0.f ? h0 : 0.f;
                const float r1 = h1 > 0.f ? h1 : 0.f;
                *(float2*)(out + (size_t)cbase * (SS * HH) + (size_t)t * HH + jb + u0) =
                    make_float2(1.f / (1.f + expf(-r0)), 1.f / (1.f + expf(-r1)));
            } else {
                *(float2*)(out + ((size_t)t * BB + cbase) * HH + jb + u0) =
                    make_float2(h0, h1);
            }
        }
        grid_barrier(nct);
    }
}

// ---------------- launch ----------------
extern "C" void kernel_launch(void* const* d_in, const int* in_sizes, int n_in,
                              void* d_out, int out_size) {
    const float* x    = (const float*)d_in[0];
    const float* Wih0 = (const float*)d_in[1];
    const float* Whh0 = (const float*)d_in[2];
    const float* bih0 = (const float*)d_in[3];
    const float* bhh0 = (const float*)d_in[4];
    const float* Wih1 = (const float*)d_in[5];
    const float* Whh1 = (const float*)d_in[6];
    const float* bih1 = (const float*)d_in[7];
    const float* bhh1 = (const float*)d_in[8];
    float* out = (float*)d_out;

    float *gx0, *gx1, *h1;
    cudaGetSymbolAddress((void**)&gx0, d_gx0);
    cudaGetSymbolAddress((void**)&gx1, d_gx1);
    cudaGetSymbolAddress((void**)&h1,  d_h1buf);

    cudaFuncSetAttribute(rec_kernel<false>,
                         cudaFuncAttributeMaxDynamicSharedMemorySize, REC_SMEM_BYTES);
    cudaFuncSetAttribute(rec_kernel<true>,
                         cudaFuncAttributeMaxDynamicSharedMemorySize, REC_SMEM_BYTES);

    dim3 gridP(G4H / 128, (BB * SS) / 64);   // (32, 256)

    proj_kernel<true><<<gridP, 256>>>(x, Wih0, bih0, bhh0, gx0, DD);
    rec_kernel<false><<<128, 256, REC_SMEM_BYTES>>>(gx0, Whh0, h1);
    proj_kernel<false><<<gridP, 256>>>(h1, Wih1, bih1, bhh1, gx1, HH);
    rec_kernel<true><<<128, 256, REC_SMEM_BYTES>>>(gx1, Whh1, out);
}

// round 3
// speedup vs baseline: 3.0307x; 1.2825x over previous
#include <cuda_runtime.h>
#include <cuda_fp16.h>
#include <cstdint>

#define HH   1024
#define BB   64
#define SS   256
#define DD   512
#define G4H  4096

// ---------------- scratch (device globals: allocation-free) ----------------
__device__ float d_gx0[(size_t)SS * BB * G4H];    // [S,B,4H] layer0 input proj
__device__ float d_gx1[(size_t)SS * BB * G4H];    // [S,B,4H] layer1 input proj
__device__ float d_h1buf[(size_t)SS * BB * HH];   // [S,B,H]  layer0 outputs (fp32)
__device__ unsigned d_hbuf16[2][BB * HH / 2];     // double-buffered h (fp16 half2)
__device__ unsigned g_cnt;
__device__ volatile unsigned g_gen;

// ---------------- helpers ----------------
__device__ __forceinline__ unsigned f2tf(float x) {
    unsigned r;
    asm("cvt.rna.tf32.f32 %0, %1;" : "=r"(r) : "f"(x));
    return r;
}

__device__ __forceinline__ void st4(unsigned* p, float4 v) {
    p[0] = f2tf(v.x); p[1] = f2tf(v.y); p[2] = f2tf(v.z); p[3] = f2tf(v.w);
}

__device__ __forceinline__ unsigned pack_h2(float a, float b) {
    __half2 h = __floats2half2_rn(a, b);
    return *(unsigned*)&h;
}

// tf32 m16n8k8 (projection kernels)
__device__ __forceinline__ void mma8(float d[4], const unsigned a[4], const unsigned b[2]) {
    asm volatile(
        "mma.sync.aligned.m16n8k8.row.col.f32.tf32.tf32.f32 "
        "{%0,%1,%2,%3},{%4,%5,%6,%7},{%8,%9},{%0,%1,%2,%3};\n"
        : "+f"(d[0]), "+f"(d[1]), "+f"(d[2]), "+f"(d[3])
        : "r"(a[0]), "r"(a[1]), "r"(a[2]), "r"(a[3]), "r"(b[0]), "r"(b[1]));
}

// fp16 m16n8k16 (recurrent kernel)
__device__ __forceinline__ void mma16h(float d[4], const unsigned a[4], const unsigned b[2]) {
    asm volatile(
        "mma.sync.aligned.m16n8k16.row.col.f32.f16.f16.f32 "
        "{%0,%1,%2,%3},{%4,%5,%6,%7},{%8,%9},{%0,%1,%2,%3};\n"
        : "+f"(d[0]), "+f"(d[1]), "+f"(d[2]), "+f"(d[3])
        : "r"(a[0]), "r"(a[1]), "r"(a[2]), "r"(a[3]), "r"(b[0]), "r"(b[1]));
}

__device__ __forceinline__ void grid_barrier(unsigned nct) {
    __threadfence();
    __syncthreads();
    if (threadIdx.x == 0) {
        const unsigned g = g_gen;
        if (atomicAdd(&g_cnt, 1u) == nct - 1u) {
            g_cnt = 0u;
            __threadfence();
            g_gen = g + 1u;
        } else {
            while (g_gen == g) __nanosleep(20);
            __threadfence();
        }
    }
    __syncthreads();
}

// ---------------- input-projection GEMM (tf32, unchanged) ----------------
template <bool REMAP>
__global__ __launch_bounds__(256) void proj_kernel(
    const float* __restrict__ A, const float* __restrict__ W,
    const float* __restrict__ bias1, const float* __restrict__ bias2,
    float* __restrict__ C, int K) {
    __shared__ unsigned As[2][64][20];
    __shared__ unsigned Bs[2][128][20];

    const int tid = threadIdx.x;
    const int lane = tid & 31, warp = tid >> 5;
    const int wm = warp >> 2, wn = warp & 3;
    const int g4 = lane >> 2, t4 = lane & 3;
    const int m0 = blockIdx.y * 64;
    const int n0 = blockIdx.x * 128;

    float acc[2][4][4];
#pragma unroll
    for (int a = 0; a < 2; a++)
#pragma unroll
        for (int b = 0; b < 4; b++)
#pragma unroll
            for (int c = 0; c < 4; c++) acc[a][b][c] = 0.f;

    const int ar = tid >> 2;
    const int ac = (tid & 3) << 2;
    const float* Ap  = A + (size_t)(m0 + ar) * K + ac;
    const float* Bp0 = W + (size_t)(n0 + ar) * K + ac;
    const float* Bp1 = W + (size_t)(n0 + ar + 64) * K + ac;
    const int KT = K >> 4;

    float4 av  = *(const float4*)Ap;
    float4 bv0 = *(const float4*)Bp0;
    float4 bv1 = *(const float4*)Bp1;
    st4(&As[0][ar][ac], av);
    st4(&Bs[0][ar][ac], bv0);
    st4(&Bs[0][ar + 64][ac], bv1);
    __syncthreads();

    int buf = 0;
    for (int kt = 0; kt < KT; kt++) {
        const int kn = (kt + 1) << 4;
        if (kt + 1 < KT) {
            av  = *(const float4*)(Ap + kn);
            bv0 = *(const float4*)(Bp0 + kn);
            bv1 = *(const float4*)(Bp1 + kn);
        }
#pragma unroll
        for (int kk = 0; kk < 2; kk++) {
            const int k8 = kk * 8;
            unsigned af[2][4], bf[4][2];
#pragma unroll
            for (int im = 0; im < 2; im++) {
                const int r = wm * 32 + im * 16;
                af[im][0] = As[buf][r + g4][k8 + t4];
                af[im][1] = As[buf][r + 8 + g4][k8 + t4];
                af[im][2] = As[buf][r + g4][k8 + 4 + t4];
                af[im][3] = As[buf][r + 8 + g4][k8 + 4 + t4];
            }
#pragma unroll
            for (int in = 0; in < 4; in++) {
                const int c = wn * 32 + in * 8;
                bf[in][0] = Bs[buf][c + g4][k8 + t4];
                bf[in][1] = Bs[buf][c + g4][k8 + 4 + t4];
            }
#pragma unroll
            for (int im = 0; im < 2; im++)
#pragma unroll
                for (int in = 0; in < 4; in++)
                    mma8(acc[im][in], af[im], bf[in]);
        }
        if (kt + 1 < KT) {
            st4(&As[buf ^ 1][ar][ac], av);
            st4(&Bs[buf ^ 1][ar][ac], bv0);
            st4(&Bs[buf ^ 1][ar + 64][ac], bv1);
        }
        __syncthreads();
        buf ^= 1;
    }

#pragma unroll
    for (int im = 0; im < 2; im++) {
#pragma unroll
        for (int in = 0; in < 4; in++) {
            const int col = n0 + wn * 32 + in * 8 + (t4 << 1);
            const float bb0 = bias1[col] + bias2[col];
            const float bb1 = bias1[col + 1] + bias2[col + 1];
            const int r0 = m0 + wm * 32 + im * 16 + g4;
            const int r1 = r0 + 8;
            size_t o0, o1;
            if (REMAP) {
                o0 = ((size_t)((r0 & (SS - 1)) * BB + (r0 >> 8))) * G4H + col;
                o1 = ((size_t)((r1 & (SS - 1)) * BB + (r1 >> 8))) * G4H + col;
            } else {
                o0 = (size_t)r0 * G4H + col;
                o1 = (size_t)r1 * G4H + col;
            }
            *(float2*)(C + o0) = make_float2(acc[im][in][0] + bb0, acc[im][in][1] + bb1);
            *(float2*)(C + o1) = make_float2(acc[im][in][2] + bb0, acc[im][in][3] + bb1);
        }
    }
}

// ---------------- persistent recurrent kernel v3 (fp16 operands) ----------
// 128 CTAs x 256 threads; CTA owns 8 hidden units x 4 gates (32 gate cols).
// W_hh slab [32 x 1024] fp16 in smem for whole kernel. h fp16 in global,
// streamed per step as 4 K-chunks of 256 (3-buffer cp.async ring, 2 groups in
// flight). gx[t+1] prefetched into smem during step t's GEMM.
// smem layout (uint words):
//   Ws  [32][516]            (fp16 half2 pairs)         16512
//   As  [3][64][132]                                    25344
//   gsm [2][64][34] (float)                              4352
//   gxs [2][64][36] (float)                              4608
//   csm [512]       (float)                               512
#define WS_STRIDE 516
#define AS_STRIDE 132
#define AS_BUF    (64 * AS_STRIDE)
#define OFF_AS    (32 * WS_STRIDE)
#define OFF_GSM   (OFF_AS + 3 * AS_BUF)
#define GSM_BUF   (64 * 34)
#define OFF_GXS   (OFF_GSM + 2 * GSM_BUF)
#define GXS_BUF   (64 * 36)
#define OFF_CSM   (OFF_GXS + 2 * GXS_BUF)
#define SMEM_WORDS (OFF_CSM + 512)
#define REC_SMEM_BYTES (SMEM_WORDS * 4)

// one chunk = 64 rows x 128 uints (256 fp16 k) ; 8 cp.async x 16B per thread
__device__ __forceinline__ void prefetch_h(const unsigned* hrow0, int chunk,
                                           unsigned* dst, int tid) {
#pragma unroll
    for (int it = 0; it < 8; it++) {
        const int s = tid + it * 256;
        const int row = s >> 5;
        const int c4 = (s & 31) << 2;
        const unsigned* src = hrow0 + (size_t)row * (HH / 2) + chunk * 128 + c4;
        unsigned d = (unsigned)__cvta_generic_to_shared(dst + row * AS_STRIDE + c4);
        asm volatile("cp.async.cg.shared.global [%0], [%1], 16;\n" :: "r"(d), "l"(src));
    }
}

// gx slice for one step: 64 batches x 32 cols fp32 = 8KB ; 2 x 16B per thread
__device__ __forceinline__ void prefetch_gx(const float* gxt, int jb,
                                            float* dst, int tid) {
#pragma unroll
    for (int it = 0; it < 2; it++) {
        const int s = tid + it * 256;
        const int b = s >> 3, rest = s & 7;
        const int gate = rest >> 1, half = rest & 1;
        const float* src = gxt + (size_t)b * G4H + gate * HH + jb + half * 4;
        unsigned d = (unsigned)__cvta_generic_to_shared(dst + b * 36 + gate * 8 + half * 4);
        asm volatile("cp.async.cg.shared.global [%0], [%1], 16;\n" :: "r"(d), "l"(src));
    }
}

template <bool FINAL>
__global__ __launch_bounds__(256) void rec_kernel(
    const float* __restrict__ gx, const float* __restrict__ Whh,
    float* __restrict__ out) {
    extern __shared__ unsigned smu[];
    unsigned* Ws  = smu;
    unsigned* Asm = smu + OFF_AS;
    float* gsm = (float*)(smu + OFF_GSM);
    float* gxs = (float*)(smu + OFF_GXS);
    float* csm = (float*)(smu + OFF_CSM);

    const int tid = threadIdx.x;
    const int lane = tid & 31, warp = tid >> 5;
    const int wk = warp >> 2;            // K-split half
    const int wm = (warp >> 1) & 1;      // M half (32 rows)
    const int wn = warp & 1;             // N half (16 cols)
    const int g4 = lane >> 2, t4 = lane & 3;
    const int jb = blockIdx.x << 3;      // 8 hidden units per CTA
    const unsigned nct = gridDim.x;

    // --- one-time: W slab -> smem fp16, zero h[0] slice + c state ---
    for (int idx = tid; idx < 32 * 512; idx += 256) {
        const int v = idx >> 9, kh = idx & 511;
        const int grow = (v >> 3) * HH + jb + (v & 7);
        const float2 w2 = *(const float2*)(Whh + (size_t)grow * HH + 2 * kh);
        Ws[v * WS_STRIDE + kh] = pack_h2(w2.x, w2.y);
    }
    {
        const int b = tid >> 2, uu = tid & 3;
        d_hbuf16[0][b * (HH / 2) + (jb >> 1) + uu] = 0u;
    }
    for (int idx = tid; idx < 512; idx += 256) csm[idx] = 0.f;

    // gx[0] into gxs buffer 0
    prefetch_gx(gx, jb, gxs, tid);
    asm volatile("cp.async.commit_group;\n");
    asm volatile("cp.async.wait_group 0;\n");
    grid_barrier(nct);

    const int cbase = tid >> 2;          // batch for cell update (0..63)
    const int u0 = (tid & 3) << 1;       // unit pair

    for (int t = 0; t < SS; t++) {
        const unsigned* hprev = d_hbuf16[t & 1];
        unsigned* hnext = d_hbuf16[(t + 1) & 1];

        float acc[2][2][4];
#pragma unroll
        for (int a = 0; a < 2; a++)
#pragma unroll
            for (int b = 0; b < 2; b++)
#pragma unroll
                for (int c = 0; c < 4; c++) acc[a][b][c] = 0.f;

        // G0 = chunk0, G1 = chunk1
        prefetch_h(hprev, 0, Asm, tid);
        asm volatile("cp.async.commit_group;\n");
        prefetch_h(hprev, 1, Asm + AS_BUF, tid);
        asm volatile("cp.async.commit_group;\n");

#pragma unroll 1
        for (int ci = 0; ci < 4; ci++) {
            if (ci < 3) { asm volatile("cp.async.wait_group 1;\n"); }
            else        { asm volatile("cp.async.wait_group 0;\n"); }
            __syncthreads();
            if (ci == 0) {
                // G2 = chunk2 + gx[t+1]
                prefetch_h(hprev, 2, Asm + 2 * AS_BUF, tid);
                if (t + 1 < SS)
                    prefetch_gx(gx + (size_t)(t + 1) * (BB * G4H), jb,
                                gxs + ((t + 1) & 1) * GXS_BUF, tid);
                asm volatile("cp.async.commit_group;\n");
            } else if (ci == 1) {
                // G3 = chunk3
                prefetch_h(hprev, 3, Asm, tid);   // reuse buffer 0
                asm volatile("cp.async.commit_group;\n");
            }
            const unsigned* Ab = Asm + (ci % 3) * AS_BUF;
#pragma unroll
            for (int kk = 0; kk < 8; kk++) {
                const int ks = wk * 64 + kk * 8;       // uint idx within chunk
                const int kw = ci * 128 + ks;          // uint idx within Ws row
                unsigned af[2][4], bf[2][2];
#pragma unroll
                for (int im = 0; im < 2; im++) {
                    const int r = wm * 32 + im * 16;
                    af[im][0] = Ab[(r + g4) * AS_STRIDE + ks + t4];
                    af[im][1] = Ab[(r + 8 + g4) * AS_STRIDE + ks + t4];
                    af[im][2] = Ab[(r + g4) * AS_STRIDE + ks + 4 + t4];
                    af[im][3] = Ab[(r + 8 + g4) * AS_STRIDE + ks + 4 + t4];
                }
#pragma unroll
                for (int in = 0; in < 2; in++) {
                    const int c = wn * 16 + in * 8;
                    bf[in][0] = Ws[(c + g4) * WS_STRIDE + kw + t4];
                    bf[in][1] = Ws[(c + g4) * WS_STRIDE + kw + 4 + t4];
                }
#pragma unroll
                for (int im = 0; im < 2; im++)
#pragma unroll
                    for (int in = 0; in < 2; in++)
                        mma16h(acc[im][in], af[im], bf[in]);
            }
        }

        // dump partials: gsm[wk][row][col]
#pragma unroll
        for (int im = 0; im < 2; im++) {
#pragma unroll
            for (int in = 0; in < 2; in++) {
                const int row = wm * 32 + im * 16 + g4;
                const int col = wn * 16 + in * 8 + (t4 << 1);
                float* gb = gsm + wk * GSM_BUF;
                *(float2*)(gb + row * 34 + col) =
                    make_float2(acc[im][in][0], acc[im][in][1]);
                *(float2*)(gb + (row + 8) * 34 + col) =
                    make_float2(acc[im][in][2], acc[im][in][3]);
            }
        }
        __syncthreads();

        // fused cell update: thread -> batch=cbase, units u0,u0+1
        {
            const float* g0 = gsm + cbase * 34;
            const float* g1 = gsm + GSM_BUF + cbase * 34;
            const float* gxp = gxs + (t & 1) * GXS_BUF + cbase * 36;
            const float gi0 = g0[u0]      + g1[u0]      + gxp[u0];
            const float gi1 = g0[u0 + 1]  + g1[u0 + 1]  + gxp[u0 + 1];
            const float gf0 = g0[8 + u0]  + g1[8 + u0]  + gxp[8 + u0];
            const float gf1 = g0[9 + u0]  + g1[9 + u0]  + gxp[9 + u0];
            const float gg0 = g0[16 + u0] + g1[16 + u0] + gxp[16 + u0];
            const float gg1 = g0[17 + u0] + g1[17 + u0] + gxp[17 + u0];
            const float go0 = g0[24 + u0] + g1[24 + u0] + gxp[24 + u0];
            const float go1 = g0[25 + u0] + g1[25 + u0] + gxp[25 + u0];

            const float i0 = 1.f / (1.f + expf(-gi0));
            const float i1 = 1.f / (1.f + expf(-gi1));
            const float f0 = 1.f / (1.f + expf(-gf0));
            const float f1 = 1.f / (1.f + expf(-gf1));
            const float z0 = tanhf(gg0);
            const float z1 = tanhf(gg1);
            const float o0 = 1.f / (1.f + expf(-go0));
            const float o1 = 1.f / (1.f + expf(-go1));

            const int ce = cbase * 8 + u0;
            const float c0 = f0 * csm[ce] + i0 * z0;
            const float c1 = f1 * csm[ce + 1] + i1 * z1;
            csm[ce] = c0;
            csm[ce + 1] = c1;
            const float h0 = o0 * tanhf(c0);
            const float h1 = o1 * tanhf(c1);

            hnext[cbase * (HH / 2) + ((jb + u0) >> 1)] = pack_h2(h0, h1);

            if (FINAL) {
                const float r0 = h0 > 0.f ? h0 : 0.f;
                const float r1 = h1 > 0.f ? h1 : 0.f;
                *(float2*)(out + (size_t)cbase * (SS * HH) + (size_t)t * HH + jb + u0) =
                    make_float2(1.f / (1.f + expf(-r0)), 1.f / (1.f + expf(-r1)));
            } else {
                *(float2*)(out + ((size_t)t * BB + cbase) * HH + jb + u0) =
                    make_float2(h0, h1);
            }
        }
        grid_barrier(nct);
    }
}

// ---------------- launch ----------------
extern "C" void kernel_launch(void* const* d_in, const int* in_sizes, int n_in,
                              void* d_out, int out_size) {
    const float* x    = (const float*)d_in[0];
    const float* Wih0 = (const float*)d_in[1];
    const float* Whh0 = (const float*)d_in[2];
    const float* bih0 = (const float*)d_in[3];
    const float* bhh0 = (const float*)d_in[4];
    const float* Wih1 = (const float*)d_in[5];
    const float* Whh1 = (const float*)d_in[6];
    const float* bih1 = (const float*)d_in[7];
    const float* bhh1 = (const float*)d_in[8];
    float* out = (float*)d_out;

    float *gx0, *gx1, *h1;
    cudaGetSymbolAddress((void**)&gx0, d_gx0);
    cudaGetSymbolAddress((void**)&gx1, d_gx1);
    cudaGetSymbolAddress((void**)&h1,  d_h1buf);

    cudaFuncSetAttribute(rec_kernel<false>,
                         cudaFuncAttributeMaxDynamicSharedMemorySize, REC_SMEM_BYTES);
    cudaFuncSetAttribute(rec_kernel<true>,
                         cudaFuncAttributeMaxDynamicSharedMemorySize, REC_SMEM_BYTES);

    dim3 gridP(G4H / 128, (BB * SS) / 64);   // (32, 256)

    proj_kernel<true><<<gridP, 256>>>(x, Wih0, bih0, bhh0, gx0, DD);
    rec_kernel<false><<<128, 256, REC_SMEM_BYTES>>>(gx0, Whh0, h1);
    proj_kernel<false><<<gridP, 256>>>(h1, Wih1, bih1, bhh1, gx1, HH);
    rec_kernel<true><<<128, 256, REC_SMEM_BYTES>>>(gx1, Whh1, out);
}

// round 5
// speedup vs baseline: 3.9116x; 1.2906x over previous
#include <cuda_runtime.h>
#include <cuda_fp16.h>
#include <cstdint>

#define HH   1024
#define BB   64
#define SS   256
#define DD   512
#define G4H  4096

// ---------------- scratch (device globals: allocation-free) ----------------
__device__ float d_gx0[(size_t)SS * BB * G4H];   // [S,B,4H] layer0 input proj
__device__ unsigned d_h1r[2][BB * HH / 2];       // h1 ring (fp16 half2)
__device__ unsigned d_h2r[2][BB * HH / 2];       // h2 ring (fp16 half2)
__device__ unsigned g_cnt;
__device__ volatile unsigned g_gen;

// ---------------- helpers ----------------
__device__ __forceinline__ unsigned f2tf(float x) {
    unsigned r;
    asm("cvt.rna.tf32.f32 %0, %1;" : "=r"(r) : "f"(x));
    return r;
}

__device__ __forceinline__ void st4(unsigned* p, float4 v) {
    p[0] = f2tf(v.x); p[1] = f2tf(v.y); p[2] = f2tf(v.z); p[3] = f2tf(v.w);
}

__device__ __forceinline__ unsigned pack_h2(float a, float b) {
    __half2 h = __floats2half2_rn(a, b);
    return *(unsigned*)&h;
}

__device__ __forceinline__ void mma8(float d[4], const unsigned a[4], const unsigned b[2]) {
    asm volatile(
        "mma.sync.aligned.m16n8k8.row.col.f32.tf32.tf32.f32 "
        "{%0,%1,%2,%3},{%4,%5,%6,%7},{%8,%9},{%0,%1,%2,%3};\n"
        : "+f"(d[0]), "+f"(d[1]), "+f"(d[2]), "+f"(d[3])
        : "r"(a[0]), "r"(a[1]), "r"(a[2]), "r"(a[3]), "r"(b[0]), "r"(b[1]));
}

__device__ __forceinline__ void mma16h(float d[4], const unsigned a[4], const unsigned b[2]) {
    asm volatile(
        "mma.sync.aligned.m16n8k16.row.col.f32.f16.f16.f32 "
        "{%0,%1,%2,%3},{%4,%5,%6,%7},{%8,%9},{%0,%1,%2,%3};\n"
        : "+f"(d[0]), "+f"(d[1]), "+f"(d[2]), "+f"(d[3])
        : "r"(a[0]), "r"(a[1]), "r"(a[2]), "r"(a[3]), "r"(b[0]), "r"(b[1]));
}

__device__ __forceinline__ void grid_barrier(unsigned nct) {
    __threadfence();
    __syncthreads();
    if (threadIdx.x == 0) {
        const unsigned g = g_gen;
        if (atomicAdd(&g_cnt, 1u) == nct - 1u) {
            g_cnt = 0u;
            __threadfence();
            g_gen = g + 1u;
        } else {
            while (g_gen == g) __nanosleep(20);
            __threadfence();
        }
    }
    __syncthreads();
}

// ---------------- input-projection GEMM (tf32, layer0 only) ----------------
__global__ __launch_bounds__(256) void proj_kernel(
    const float* __restrict__ A, const float* __restrict__ W,
    const float* __restrict__ bias1, const float* __restrict__ bias2,
    float* __restrict__ C, int K) {
    __shared__ unsigned As[2][64][20];
    __shared__ unsigned Bs[2][128][20];

    const int tid = threadIdx.x;
    const int lane = tid & 31, warp = tid >> 5;
    const int wm = warp >> 2, wn = warp & 3;
    const int g4 = lane >> 2, t4 = lane & 3;
    const int m0 = blockIdx.y * 64;
    const int n0 = blockIdx.x * 128;

    float acc[2][4][4];
#pragma unroll
    for (int a = 0; a < 2; a++)
#pragma unroll
        for (int b = 0; b < 4; b++)
#pragma unroll
            for (int c = 0; c < 4; c++) acc[a][b][c] = 0.f;

    const int ar = tid >> 2;
    const int ac = (tid & 3) << 2;
    const float* Ap  = A + (size_t)(m0 + ar) * K + ac;
    const float* Bp0 = W + (size_t)(n0 + ar) * K + ac;
    const float* Bp1 = W + (size_t)(n0 + ar + 64) * K + ac;
    const int KT = K >> 4;

    float4 av  = *(const float4*)Ap;
    float4 bv0 = *(const float4*)Bp0;
    float4 bv1 = *(const float4*)Bp1;
    st4(&As[0][ar][ac], av);
    st4(&Bs[0][ar][ac], bv0);
    st4(&Bs[0][ar + 64][ac], bv1);
    __syncthreads();

    int buf = 0;
    for (int kt = 0; kt < KT; kt++) {
        const int kn = (kt + 1) << 4;
        if (kt + 1 < KT) {
            av  = *(const float4*)(Ap + kn);
            bv0 = *(const float4*)(Bp0 + kn);
            bv1 = *(const float4*)(Bp1 + kn);
        }
#pragma unroll
        for (int kk = 0; kk < 2; kk++) {
            const int k8 = kk * 8;
            unsigned af[2][4], bf[4][2];
#pragma unroll
            for (int im = 0; im < 2; im++) {
                const int r = wm * 32 + im * 16;
                af[im][0] = As[buf][r + g4][k8 + t4];
                af[im][1] = As[buf][r + 8 + g4][k8 + t4];
                af[im][2] = As[buf][r + g4][k8 + 4 + t4];
                af[im][3] = As[buf][r + 8 + g4][k8 + 4 + t4];
            }
#pragma unroll
            for (int in = 0; in < 4; in++) {
                const int c = wn * 32 + in * 8;
                bf[in][0] = Bs[buf][c + g4][k8 + t4];
                bf[in][1] = Bs[buf][c + g4][k8 + 4 + t4];
            }
#pragma unroll
            for (int im = 0; im < 2; im++)
#pragma unroll
                for (int in = 0; in < 4; in++)
                    mma8(acc[im][in], af[im], bf[in]);
        }
        if (kt + 1 < KT) {
            st4(&As[buf ^ 1][ar][ac], av);
            st4(&Bs[buf ^ 1][ar][ac], bv0);
            st4(&Bs[buf ^ 1][ar + 64][ac], bv1);
        }
        __syncthreads();
        buf ^= 1;
    }

#pragma unroll
    for (int im = 0; im < 2; im++) {
#pragma unroll
        for (int in = 0; in < 4; in++) {
            const int col = n0 + wn * 32 + in * 8 + (t4 << 1);
            const float bb0 = bias1[col] + bias2[col];
            const float bb1 = bias1[col + 1] + bias2[col + 1];
            const int r0 = m0 + wm * 32 + im * 16 + g4;
            const int r1 = r0 + 8;
            // row m = b*S+s  ->  gx[(s*B+b)]
            const size_t o0 = ((size_t)((r0 & (SS - 1)) * BB + (r0 >> 8))) * G4H + col;
            const size_t o1 = ((size_t)((r1 & (SS - 1)) * BB + (r1 >> 8))) * G4H + col;
            *(float2*)(C + o0) = make_float2(acc[im][in][0] + bb0, acc[im][in][1] + bb1);
            *(float2*)(C + o1) = make_float2(acc[im][in][2] + bb0, acc[im][in][3] + bb1);
        }
    }
}

// ---------------- fused 2-layer persistent recurrent kernel ----------------
// 128 CTAs x 256 threads. CTA owns 8 hidden units (jb) of BOTH layers.
// Per phase t (0..256):
//   layer0: h1[t]   = cell( gx0[t] + W_hh0 @ h1[t-1] )                (t<256)
//   layer1: h2[t-1] = cell( [W_ih1;W_hh1] @ [h1[t-1]; h2[t-2]] + b )  (t>0)
// Both GEMMs share the streamed h1[t-1] operand. One grid barrier per phase.
// smem (uints): Ws0[32][514] | Ws1[32][1026] | As[2][64][68] (gsm unioned)
#define WS0_STRIDE 514
#define WS1_STRIDE 1026
#define OFF_WS1   (32 * WS0_STRIDE)                 // 16448
#define OFF_AS    (OFF_WS1 + 32 * WS1_STRIDE)       // 49280
#define AS_STRIDE 68
#define AS_BUF    (64 * AS_STRIDE)                  // 4352
#define SMEM_WORDS (OFF_AS + 2 * AS_BUF)            // 57984
#define REC_SMEM_BYTES (SMEM_WORDS * 4)             // 231936 (512B under limit)
#define GSM_SEC   (64 * 34)                         // 2176 floats per section

// one chunk = 64 rows x 64 uints (128 fp16 k) = 16KB ; 4 x 16B per thread
__device__ __forceinline__ void prefetch_chunk(const unsigned* src0, int chunkk,
                                               unsigned* dst, int tid) {
#pragma unroll
    for (int it = 0; it < 4; it++) {
        const int s = tid + it * 256;
        const int row = s >> 4;
        const int c4 = (s & 15) << 2;
        const unsigned* src = src0 + (size_t)row * (HH / 2) + chunkk * 64 + c4;
        unsigned d = (unsigned)__cvta_generic_to_shared(dst + row * AS_STRIDE + c4);
        asm volatile("cp.async.cg.shared.global [%0], [%1], 16;\n" :: "r"(d), "l"(src));
    }
    asm volatile("cp.async.commit_group;\n");
}

__global__ __launch_bounds__(256) void fused_rec(
    const float* __restrict__ gx, const float* __restrict__ Whh0,
    const float* __restrict__ Wih1, const float* __restrict__ Whh1,
    const float* __restrict__ bih1, const float* __restrict__ bhh1,
    float* __restrict__ out) {
    extern __shared__ unsigned smu[];
    unsigned* Ws0 = smu;
    unsigned* Ws1 = smu + OFF_WS1;
    unsigned* Asm = smu + OFF_AS;
    float* gsm = (float*)(smu + OFF_AS);   // union: valid after GEMM of a phase

    const int tid = threadIdx.x;
    const int lane = tid & 31, warp = tid >> 5;
    const int wk = warp >> 2;            // K-split half
    const int wm = (warp >> 1) & 1;      // M half (32 rows)
    const int wn = warp & 1;             // N half (16 cols)
    const int g4 = lane >> 2, t4 = lane & 3;
    const int jb = blockIdx.x << 3;      // 8 hidden units per CTA
    const unsigned nct = gridDim.x;

    // --- one-time init: W slabs (fp16), zero ring slots, biases to regs ---
    for (int idx = tid; idx < 32 * 512; idx += 256) {
        const int v = idx >> 9, kh = idx & 511;
        const int grow = (v >> 3) * HH + jb + (v & 7);
        const float2 w2 = *(const float2*)(Whh0 + (size_t)grow * HH + 2 * kh);
        Ws0[v * WS0_STRIDE + kh] = pack_h2(w2.x, w2.y);
    }
    for (int idx = tid; idx < 32 * 1024; idx += 256) {
        const int v = idx >> 10, kh = idx & 1023;
        const int grow = (v >> 3) * HH + jb + (v & 7);
        float2 w2;
        if (kh < 512) w2 = *(const float2*)(Wih1 + (size_t)grow * HH + 2 * kh);
        else          w2 = *(const float2*)(Whh1 + (size_t)grow * HH + 2 * (kh - 512));
        Ws1[v * WS1_STRIDE + kh] = pack_h2(w2.x, w2.y);
    }
    {
        const int b = tid >> 2, q = tid & 3;
        d_h1r[0][b * (HH / 2) + (jb >> 1) + q] = 0u;
        d_h1r[1][b * (HH / 2) + (jb >> 1) + q] = 0u;
        d_h2r[0][b * (HH / 2) + (jb >> 1) + q] = 0u;
        d_h2r[1][b * (HH / 2) + (jb >> 1) + q] = 0u;
    }

    const int cbase = tid >> 2;          // batch handled in cell update
    const int u0 = (tid & 3) << 1;       // unit pair

    float bs[8];                          // layer1 per-gate biases
#pragma unroll
    for (int g = 0; g < 4; g++) {
        bs[2 * g]     = bih1[g * HH + jb + u0]     + bhh1[g * HH + jb + u0];
        bs[2 * g + 1] = bih1[g * HH + jb + u0 + 1] + bhh1[g * HH + jb + u0 + 1];
    }

    float c0a = 0.f, c0b = 0.f;          // layer0 cell state (this thread's pair)
    float c1a = 0.f, c1b = 0.f;          // layer1 cell state

    grid_barrier(nct);

#pragma unroll 1
    for (int t = 0; t <= SS; t++) {
        const unsigned* h1p = d_h1r[(t + 1) & 1];   // h1[t-1]
        unsigned* h1n = d_h1r[t & 1];               // h1[t]
        const unsigned* h2p = d_h2r[t & 1];         // h2[t-2]
        unsigned* h2n = d_h2r[(t + 1) & 1];         // h2[t-1]

        // hoist gx0[t] (lands during GEMM)
        float2 gxi, gxf, gxg, gxo;
        if (t < SS) {
            const float* gp = gx + (size_t)t * (BB * G4H) + (size_t)cbase * G4H + jb + u0;
            gxi = *(const float2*)(gp);
            gxf = *(const float2*)(gp + HH);
            gxg = *(const float2*)(gp + 2 * HH);
            gxo = *(const float2*)(gp + 3 * HH);
        }

        float acc[2][2][2][4];   // [layer][im][in][4]
#pragma unroll
        for (int L = 0; L < 2; L++)
#pragma unroll
            for (int a = 0; a < 2; a++)
#pragma unroll
                for (int b = 0; b < 2; b++)
#pragma unroll
                    for (int c = 0; c < 4; c++) acc[L][a][b][c] = 0.f;

        prefetch_chunk(h1p, 0, Asm, tid);
        prefetch_chunk(h1p, 1, Asm + AS_BUF, tid);

#pragma unroll 1
        for (int c = 0; c < 16; c++) {
            if (c < 15) { asm volatile("cp.async.wait_group 1;\n"); }
            else        { asm volatile("cp.async.wait_group 0;\n"); }
            __syncthreads();
            const unsigned* Ab = Asm + (c & 1) * AS_BUF;
            const int kwbase = c * 64 + wk * 32;
#pragma unroll
            for (int kk = 0; kk < 4; kk++) {
                const int ks = wk * 32 + kk * 8;
                const int kw = kwbase + kk * 8;
                unsigned af[2][4];
#pragma unroll
                for (int im = 0; im < 2; im++) {
                    const int r = wm * 32 + im * 16;
                    af[im][0] = Ab[(r + g4) * AS_STRIDE + ks + t4];
                    af[im][1] = Ab[(r + 8 + g4) * AS_STRIDE + ks + t4];
                    af[im][2] = Ab[(r + g4) * AS_STRIDE + ks + 4 + t4];
                    af[im][3] = Ab[(r + 8 + g4) * AS_STRIDE + ks + 4 + t4];
                }
                // layer1 (always): Ws1 over concat K
                {
                    unsigned bf[2][2];
#pragma unroll
                    for (int in = 0; in < 2; in++) {
                        const int cc = wn * 16 + in * 8;
                        bf[in][0] = Ws1[(cc + g4) * WS1_STRIDE + kw + t4];
                        bf[in][1] = Ws1[(cc + g4) * WS1_STRIDE + kw + 4 + t4];
                    }
#pragma unroll
                    for (int im = 0; im < 2; im++)
#pragma unroll
                        for (int in = 0; in < 2; in++)
                            mma16h(acc[1][im][in], af[im], bf[in]);
                }
                // layer0 (chunks 0-7 only: kw < 512)
                if (c < 8) {
                    unsigned bf[2][2];
#pragma unroll
                    for (int in = 0; in < 2; in++) {
                        const int cc = wn * 16 + in * 8;
                        bf[in][0] = Ws0[(cc + g4) * WS0_STRIDE + kw + t4];
                        bf[in][1] = Ws0[(cc + g4) * WS0_STRIDE + kw + 4 + t4];
                    }
#pragma unroll
                    for (int im = 0; im < 2; im++)
#pragma unroll
                        for (int in = 0; in < 2; in++)
                            mma16h(acc[0][im][in], af[im], bf[in]);
                }
            }
            __syncthreads();
            if (c + 2 < 16) {
                const int nc = c + 2;
                prefetch_chunk(nc < 8 ? h1p : h2p, nc & 7, Asm + (c & 1) * AS_BUF, tid);
            }
        }

        // dump partials into gsm (unioned over As): section = layer*2 + wk
#pragma unroll
        for (int L = 0; L < 2; L++) {
            float* gb = gsm + (L * 2 + wk) * GSM_SEC;
#pragma unroll
            for (int im = 0; im < 2; im++) {
#pragma unroll
                for (int in = 0; in < 2; in++) {
                    const int row = wm * 32 + im * 16 + g4;
                    const int col = wn * 16 + in * 8 + (t4 << 1);
                    *(float2*)(gb + row * 34 + col) =
                        make_float2(acc[L][im][in][0], acc[L][im][in][1]);
                    *(float2*)(gb + (row + 8) * 34 + col) =
                        make_float2(acc[L][im][in][2], acc[L][im][in][3]);
                }
            }
        }
        __syncthreads();

        // ---- layer0 cell update ----
        if (t < SS) {
            const float* s0 = gsm + cbase * 34;
            const float* s1 = gsm + GSM_SEC + cbase * 34;
            const float gi0 = s0[u0]      + s1[u0]      + gxi.x;
            const float gi1 = s0[u0 + 1]  + s1[u0 + 1]  + gxi.y;
            const float gf0 = s0[8 + u0]  + s1[8 + u0]  + gxf.x;
            const float gf1 = s0[9 + u0]  + s1[9 + u0]  + gxf.y;
            const float gg0 = s0[16 + u0] + s1[16 + u0] + gxg.x;
            const float gg1 = s0[17 + u0] + s1[17 + u0] + gxg.y;
            const float go0 = s0[24 + u0] + s1[24 + u0] + gxo.x;
            const float go1 = s0[25 + u0] + s1[25 + u0] + gxo.y;
            const float i0 = 1.f / (1.f + expf(-gi0));
            const float i1 = 1.f / (1.f + expf(-gi1));
            const float f0 = 1.f / (1.f + expf(-gf0));
            const float f1 = 1.f / (1.f + expf(-gf1));
            const float z0 = tanhf(gg0);
            const float z1 = tanhf(gg1);
            const float o0 = 1.f / (1.f + expf(-go0));
            const float o1 = 1.f / (1.f + expf(-go1));
            c0a = f0 * c0a + i0 * z0;
            c0b = f1 * c0b + i1 * z1;
            const float h0 = o0 * tanhf(c0a);
            const float h1 = o1 * tanhf(c0b);
            h1n[cbase * (HH / 2) + ((jb + u0) >> 1)] = pack_h2(h0, h1);
        }

        // ---- layer1 cell update (computes h2[t-1]) ----
        if (t > 0) {
            const float* s2 = gsm + 2 * GSM_SEC + cbase * 34;
            const float* s3 = gsm + 3 * GSM_SEC + cbase * 34;
            const float gi0 = s2[u0]      + s3[u0]      + bs[0];
            const float gi1 = s2[u0 + 1]  + s3[u0 + 1]  + bs[1];
            const float gf0 = s2[8 + u0]  + s3[8 + u0]  + bs[2];
            const float gf1 = s2[9 + u0]  + s3[9 + u0]  + bs[3];
            const float gg0 = s2[16 + u0] + s3[16 + u0] + bs[4];
            const float gg1 = s2[17 + u0] + s3[17 + u0] + bs[5];
            const float go0 = s2[24 + u0] + s3[24 + u0] + bs[6];
            const float go1 = s2[25 + u0] + s3[25 + u0] + bs[7];
            const float i0 = 1.f / (1.f + expf(-gi0));
            const float i1 = 1.f / (1.f + expf(-gi1));
            const float f0 = 1.f / (1.f + expf(-gf0));
            const float f1 = 1.f / (1.f + expf(-gf1));
            const float z0 = tanhf(gg0);
            const float z1 = tanhf(gg1);
            const float o0 = 1.f / (1.f + expf(-go0));
            const float o1 = 1.f / (1.f + expf(-go1));
            c1a = f0 * c1a + i0 * z0;
            c1b = f1 * c1b + i1 * z1;
            const float h0 = o0 * tanhf(c1a);
            const float h1 = o1 * tanhf(c1b);
            h2n[cbase * (HH / 2) + ((jb + u0) >> 1)] = pack_h2(h0, h1);
            const float r0 = h0 > 0.f ? h0 : 0.f;
            const float r1 = h1 > 0.f ? h1 : 0.f;
            *(float2*)(out + (size_t)cbase * (SS * HH) + (size_t)(t - 1) * HH + jb + u0) =
                make_float2(1.f / (1.f + expf(-r0)), 1.f / (1.f + expf(-r1)));
        }

        grid_barrier(nct);
    }
}

// ---------------- launch ----------------
extern "C" void kernel_launch(void* const* d_in, const int* in_sizes, int n_in,
                              void* d_out, int out_size) {
    const float* x    = (const float*)d_in[0];
    const float* Wih0 = (const float*)d_in[1];
    const float* Whh0 = (const float*)d_in[2];
    const float* bih0 = (const float*)d_in[3];
    const float* bhh0 = (const float*)d_in[4];
    const float* Wih1 = (const float*)d_in[5];
    const float* Whh1 = (const float*)d_in[6];
    const float* bih1 = (const float*)d_in[7];
    const float* bhh1 = (const float*)d_in[8];
    float* out = (float*)d_out;

    float* gx0;
    cudaGetSymbolAddress((void**)&gx0, d_gx0);

    cudaFuncSetAttribute(fused_rec,
                         cudaFuncAttributeMaxDynamicSharedMemorySize, REC_SMEM_BYTES);

    dim3 gridP(G4H / 128, (BB * SS) / 64);   // (32, 256)

    proj_kernel<<<gridP, 256>>>(x, Wih0, bih0, bhh0, gx0, DD);
    fused_rec<<<128, 256, REC_SMEM_BYTES>>>(gx0, Whh0, Wih1, Whh1, bih1, bhh1, out);
}

// round 6
// speedup vs baseline: 3.9849x; 1.0187x over previous
#include <cuda_runtime.h>
#include <cuda_fp16.h>
#include <cstdint>

#define HH   1024
#define BB   64
#define SS   256
#define DD   512
#define G4H  4096

// ---------------- scratch (device globals: allocation-free) ----------------
__device__ float d_gx0[(size_t)SS * BB * G4H];   // [S,B,4H] layer0 input proj
__device__ unsigned d_h1r[2][BB * HH / 2];       // h1 ring (fp16 half2)
__device__ unsigned d_h2r[2][BB * HH / 2];       // h2 ring (fp16 half2)
__device__ unsigned g_cnt;
__device__ volatile unsigned g_gen;

// ---------------- helpers ----------------
__device__ __forceinline__ unsigned f2tf(float x) {
    unsigned r;
    asm("cvt.rna.tf32.f32 %0, %1;" : "=r"(r) : "f"(x));
    return r;
}

__device__ __forceinline__ void st4(unsigned* p, float4 v) {
    p[0] = f2tf(v.x); p[1] = f2tf(v.y); p[2] = f2tf(v.z); p[3] = f2tf(v.w);
}

__device__ __forceinline__ unsigned pack_h2(float a, float b) {
    __half2 h = __floats2half2_rn(a, b);
    return *(unsigned*)&h;
}

__device__ __forceinline__ void mma8(float d[4], const unsigned a[4], const unsigned b[2]) {
    asm volatile(
        "mma.sync.aligned.m16n8k8.row.col.f32.tf32.tf32.f32 "
        "{%0,%1,%2,%3},{%4,%5,%6,%7},{%8,%9},{%0,%1,%2,%3};\n"
        : "+f"(d[0]), "+f"(d[1]), "+f"(d[2]), "+f"(d[3])
        : "r"(a[0]), "r"(a[1]), "r"(a[2]), "r"(a[3]), "r"(b[0]), "r"(b[1]));
}

__device__ __forceinline__ void mma16h(float d[4], const unsigned a[4], const unsigned b[2]) {
    asm volatile(
        "mma.sync.aligned.m16n8k16.row.col.f32.f16.f16.f32 "
        "{%0,%1,%2,%3},{%4,%5,%6,%7},{%8,%9},{%0,%1,%2,%3};\n"
        : "+f"(d[0]), "+f"(d[1]), "+f"(d[2]), "+f"(d[3])
        : "r"(a[0]), "r"(a[1]), "r"(a[2]), "r"(a[3]), "r"(b[0]), "r"(b[1]));
}

__device__ __forceinline__ void ldsm_x4(unsigned (&r)[4], unsigned addr) {
    asm volatile(
        "ldmatrix.sync.aligned.m8n8.x4.shared.b16 {%0,%1,%2,%3}, [%4];\n"
        : "=r"(r[0]), "=r"(r[1]), "=r"(r[2]), "=r"(r[3]) : "r"(addr));
}

__device__ __forceinline__ void grid_barrier(unsigned nct) {
    __threadfence();
    __syncthreads();
    if (threadIdx.x == 0) {
        const unsigned g = g_gen;
        if (atomicAdd(&g_cnt, 1u) == nct - 1u) {
            g_cnt = 0u;
            __threadfence();
            g_gen = g + 1u;
        } else {
            while (g_gen == g) __nanosleep(20);
            __threadfence();
        }
    }
    __syncthreads();
}

// ---------------- input-projection GEMM (tf32, layer0 only) ----------------
__global__ __launch_bounds__(256) void proj_kernel(
    const float* __restrict__ A, const float* __restrict__ W,
    const float* __restrict__ bias1, const float* __restrict__ bias2,
    float* __restrict__ C, int K) {
    __shared__ unsigned As[2][64][20];
    __shared__ unsigned Bs[2][128][20];

    const int tid = threadIdx.x;
    const int lane = tid & 31, warp = tid >> 5;
    const int wm = warp >> 2, wn = warp & 3;
    const int g4 = lane >> 2, t4 = lane & 3;
    const int m0 = blockIdx.y * 64;
    const int n0 = blockIdx.x * 128;

    float acc[2][4][4];
#pragma unroll
    for (int a = 0; a < 2; a++)
#pragma unroll
        for (int b = 0; b < 4; b++)
#pragma unroll
            for (int c = 0; c < 4; c++) acc[a][b][c] = 0.f;

    const int ar = tid >> 2;
    const int ac = (tid & 3) << 2;
    const float* Ap  = A + (size_t)(m0 + ar) * K + ac;
    const float* Bp0 = W + (size_t)(n0 + ar) * K + ac;
    const float* Bp1 = W + (size_t)(n0 + ar + 64) * K + ac;
    const int KT = K >> 4;

    float4 av  = *(const float4*)Ap;
    float4 bv0 = *(const float4*)Bp0;
    float4 bv1 = *(const float4*)Bp1;
    st4(&As[0][ar][ac], av);
    st4(&Bs[0][ar][ac], bv0);
    st4(&Bs[0][ar + 64][ac], bv1);
    __syncthreads();

    int buf = 0;
    for (int kt = 0; kt < KT; kt++) {
        const int kn = (kt + 1) << 4;
        if (kt + 1 < KT) {
            av  = *(const float4*)(Ap + kn);
            bv0 = *(const float4*)(Bp0 + kn);
            bv1 = *(const float4*)(Bp1 + kn);
        }
#pragma unroll
        for (int kk = 0; kk < 2; kk++) {
            const int k8 = kk * 8;
            unsigned af[2][4], bf[4][2];
#pragma unroll
            for (int im = 0; im < 2; im++) {
                const int r = wm * 32 + im * 16;
                af[im][0] = As[buf][r + g4][k8 + t4];
                af[im][1] = As[buf][r + 8 + g4][k8 + t4];
                af[im][2] = As[buf][r + g4][k8 + 4 + t4];
                af[im][3] = As[buf][r + 8 + g4][k8 + 4 + t4];
            }
#pragma unroll
            for (int in = 0; in < 4; in++) {
                const int c = wn * 32 + in * 8;
                bf[in][0] = Bs[buf][c + g4][k8 + t4];
                bf[in][1] = Bs[buf][c + g4][k8 + 4 + t4];
            }
#pragma unroll
            for (int im = 0; im < 2; im++)
#pragma unroll
                for (int in = 0; in < 4; in++)
                    mma8(acc[im][in], af[im], bf[in]);
        }
        if (kt + 1 < KT) {
            st4(&As[buf ^ 1][ar][ac], av);
            st4(&Bs[buf ^ 1][ar][ac], bv0);
            st4(&Bs[buf ^ 1][ar + 64][ac], bv1);
        }
        __syncthreads();
        buf ^= 1;
    }

#pragma unroll
    for (int im = 0; im < 2; im++) {
#pragma unroll
        for (int in = 0; in < 4; in++) {
            const int col = n0 + wn * 32 + in * 8 + (t4 << 1);
            const float bb0 = bias1[col] + bias2[col];
            const float bb1 = bias1[col + 1] + bias2[col + 1];
            const int r0 = m0 + wm * 32 + im * 16 + g4;
            const int r1 = r0 + 8;
            // row m = b*S+s  ->  gx[(s*B+b)]
            const size_t o0 = ((size_t)((r0 & (SS - 1)) * BB + (r0 >> 8))) * G4H + col;
            const size_t o1 = ((size_t)((r1 & (SS - 1)) * BB + (r1 >> 8))) * G4H + col;
            *(float2*)(C + o0) = make_float2(acc[im][in][0] + bb0, acc[im][in][1] + bb1);
            *(float2*)(C + o1) = make_float2(acc[im][in][2] + bb0, acc[im][in][3] + bb1);
        }
    }
}

// ---------------- fused 2-layer persistent recurrent kernel (ldmatrix) ----
// 128 CTAs x 256 threads. CTA owns 8 hidden units (jb) of BOTH layers.
// Per phase t (0..256):
//   layer0: h1[t]   = cell( gx0[t] + W_hh0 @ h1[t-1] )                (t<256)
//   layer1: h2[t-1] = cell( [W_ih1;W_hh1] @ [h1[t-1]; h2[t-2]] + b )  (t>0)
// W slabs XOR-swizzled (kw ^= (n&7)<<2) at natural strides 512/1024 words.
// All fragments loaded via ldmatrix.x4 (conflict-free).
// smem (uints): Ws0[32][512] | Ws1[32][1024] | As[2][64][68] (gsm unioned)
#define WS0_STRIDE 512
#define WS1_STRIDE 1024
#define OFF_WS1   (32 * WS0_STRIDE)                 // 16384
#define OFF_AS    (OFF_WS1 + 32 * WS1_STRIDE)       // 49152
#define AS_STRIDE 68
#define AS_BUF    (64 * AS_STRIDE)                  // 4352
#define SMEM_WORDS (OFF_AS + 2 * AS_BUF)            // 57856
#define REC_SMEM_BYTES (SMEM_WORDS * 4)             // 231424 (< 231936 proven)
#define GSM_SEC   (64 * 34)                         // 2176 floats per section

// one chunk = 64 rows x 64 uints (128 fp16 k) = 16KB ; 4 x 16B per thread
__device__ __forceinline__ void prefetch_chunk(const unsigned* src0, int chunkk,
                                               unsigned* dst, int tid) {
#pragma unroll
    for (int it = 0; it < 4; it++) {
        const int s = tid + it * 256;
        const int row = s >> 4;
        const int c4 = (s & 15) << 2;
        const unsigned* src = src0 + (size_t)row * (HH / 2) + chunkk * 64 + c4;
        unsigned d = (unsigned)__cvta_generic_to_shared(dst + row * AS_STRIDE + c4);
        asm volatile("cp.async.cg.shared.global [%0], [%1], 16;\n" :: "r"(d), "l"(src));
    }
    asm volatile("cp.async.commit_group;\n");
}

__global__ __launch_bounds__(256) void fused_rec(
    const float* __restrict__ gx, const float* __restrict__ Whh0,
    const float* __restrict__ Wih1, const float* __restrict__ Whh1,
    const float* __restrict__ bih1, const float* __restrict__ bhh1,
    float* __restrict__ out) {
    extern __shared__ unsigned smu[];
    unsigned* Ws0 = smu;
    unsigned* Ws1 = smu + OFF_WS1;
    unsigned* Asm = smu + OFF_AS;
    float* gsm = (float*)(smu + OFF_AS);   // union: valid after GEMM of a phase

    const int tid = threadIdx.x;
    const int lane = tid & 31, warp = tid >> 5;
    const int wk = warp >> 2;            // K-split half
    const int wm = (warp >> 1) & 1;      // M half (32 rows)
    const int wn = warp & 1;             // N half (16 cols)
    const int jb = blockIdx.x << 3;      // 8 hidden units per CTA
    const unsigned nct = gridDim.x;

    // --- one-time init: W slabs (fp16, swizzled), zero rings, biases ---
    for (int idx = tid; idx < 32 * 512; idx += 256) {
        const int v = idx >> 9, kh = idx & 511;
        const int grow = (v >> 3) * HH + jb + (v & 7);
        const float2 w2 = *(const float2*)(Whh0 + (size_t)grow * HH + 2 * kh);
        Ws0[v * WS0_STRIDE + (kh ^ ((v & 7) << 2))] = pack_h2(w2.x, w2.y);
    }
    for (int idx = tid; idx < 32 * 1024; idx += 256) {
        const int v = idx >> 10, kh = idx & 1023;
        const int grow = (v >> 3) * HH + jb + (v & 7);
        float2 w2;
        if (kh < 512) w2 = *(const float2*)(Wih1 + (size_t)grow * HH + 2 * kh);
        else          w2 = *(const float2*)(Whh1 + (size_t)grow * HH + 2 * (kh - 512));
        Ws1[v * WS1_STRIDE + (kh ^ ((v & 7) << 2))] = pack_h2(w2.x, w2.y);
    }
    {
        const int b = tid >> 2, q = tid & 3;
        d_h1r[0][b * (HH / 2) + (jb >> 1) + q] = 0u;
        d_h1r[1][b * (HH / 2) + (jb >> 1) + q] = 0u;
        d_h2r[0][b * (HH / 2) + (jb >> 1) + q] = 0u;
        d_h2r[1][b * (HH / 2) + (jb >> 1) + q] = 0u;
    }

    const int cbase = tid >> 2;          // batch handled in cell update
    const int u0 = (tid & 3) << 1;       // unit pair

    float bs[8];                          // layer1 per-gate biases
#pragma unroll
    for (int g = 0; g < 4; g++) {
        bs[2 * g]     = bih1[g * HH + jb + u0]     + bhh1[g * HH + jb + u0];
        bs[2 * g + 1] = bih1[g * HH + jb + u0 + 1] + bhh1[g * HH + jb + u0 + 1];
    }

    // --- lane-constant ldmatrix addressing ---
    const unsigned base_u = (unsigned)__cvta_generic_to_shared(smu);
    const int r8   = lane & 7;
    const int sel8 = (lane & 8) ? 8 : 0;      // +8 rows for matrices 1,3
    const int selk = (lane & 16) ? 4 : 0;     // +8 fp16 k for matrices 2,3
    const int szB  = selk ^ (r8 << 2);        // swizzled k-offset part for B
    const unsigned offA0 = (unsigned)((wm * 32 + r8 + sel8) * AS_STRIDE + selk);
    const unsigned offA1 = offA0 + 16 * AS_STRIDE;
    const unsigned abase[2] = { base_u + OFF_AS * 4,
                                base_u + (OFF_AS + AS_BUF) * 4 };
    const unsigned b1base = base_u + (OFF_WS1 + (wn * 16 + r8 + sel8) * WS1_STRIDE) * 4;
    const unsigned b0base = base_u + ((wn * 16 + r8 + sel8) * WS0_STRIDE) * 4;

    float c0a = 0.f, c0b = 0.f;          // layer0 cell state (this thread's pair)
    float c1a = 0.f, c1b = 0.f;          // layer1 cell state

    grid_barrier(nct);

#pragma unroll 1
    for (int t = 0; t <= SS; t++) {
        const unsigned* h1p = d_h1r[(t + 1) & 1];   // h1[t-1]
        unsigned* h1n = d_h1r[t & 1];               // h1[t]
        const unsigned* h2p = d_h2r[t & 1];         // h2[t-2]
        unsigned* h2n = d_h2r[(t + 1) & 1];         // h2[t-1]

        // hoist gx0[t] (lands during GEMM)
        float2 gxi, gxf, gxg, gxo;
        if (t < SS) {
            const float* gp = gx + (size_t)t * (BB * G4H) + (size_t)cbase * G4H + jb + u0;
            gxi = *(const float2*)(gp);
            gxf = *(const float2*)(gp + HH);
            gxg = *(const float2*)(gp + 2 * HH);
            gxo = *(const float2*)(gp + 3 * HH);
        }

        float acc[2][2][2][4];   // [layer][im][in][4]
#pragma unroll
        for (int L = 0; L < 2; L++)
#pragma unroll
            for (int a = 0; a < 2; a++)
#pragma unroll
                for (int b = 0; b < 2; b++)
#pragma unroll
                    for (int c = 0; c < 4; c++) acc[L][a][b][c] = 0.f;

        prefetch_chunk(h1p, 0, Asm, tid);
        prefetch_chunk(h1p, 1, Asm + AS_BUF, tid);

#pragma unroll 1
        for (int c = 0; c < 16; c++) {
            if (c < 15) { asm volatile("cp.async.wait_group 1;\n"); }
            else        { asm volatile("cp.async.wait_group 0;\n"); }
            __syncthreads();
            const unsigned ab = abase[c & 1];
            const int kwarp = c * 64 + wk * 32;
#pragma unroll
            for (int kk = 0; kk < 4; kk++) {
                const int ks = wk * 32 + kk * 8;
                const int kw = kwarp + kk * 8;
                unsigned af0[4], af1[4];
                ldsm_x4(af0, ab + ((offA0 + ks) << 2));
                ldsm_x4(af1, ab + ((offA1 + ks) << 2));
                // layer1 (always)
                {
                    unsigned bq[4];
                    ldsm_x4(bq, b1base + ((unsigned)(kw ^ szB) << 2));
                    unsigned bfa[2] = { bq[0], bq[2] };
                    unsigned bfb[2] = { bq[1], bq[3] };
                    mma16h(acc[1][0][0], af0, bfa);
                    mma16h(acc[1][0][1], af0, bfb);
                    mma16h(acc[1][1][0], af1, bfa);
                    mma16h(acc[1][1][1], af1, bfb);
                }
                // layer0 (chunks 0-7 only)
                if (c < 8) {
                    unsigned bq[4];
                    ldsm_x4(bq, b0base + ((unsigned)(kw ^ szB) << 2));
                    unsigned bfa[2] = { bq[0], bq[2] };
                    unsigned bfb[2] = { bq[1], bq[3] };
                    mma16h(acc[0][0][0], af0, bfa);
                    mma16h(acc[0][0][1], af0, bfb);
                    mma16h(acc[0][1][0], af1, bfa);
                    mma16h(acc[0][1][1], af1, bfb);
                }
            }
            __syncthreads();
            if (c + 2 < 16) {
                const int nc = c + 2;
                prefetch_chunk(nc < 8 ? h1p : h2p, nc & 7, Asm + (c & 1) * AS_BUF, tid);
            }
        }

        // dump partials into gsm (unioned over As): section = layer*2 + wk
        {
            const int g4 = lane >> 2, t4 = lane & 3;
#pragma unroll
            for (int L = 0; L < 2; L++) {
                float* gb = gsm + (L * 2 + wk) * GSM_SEC;
#pragma unroll
                for (int im = 0; im < 2; im++) {
#pragma unroll
                    for (int in = 0; in < 2; in++) {
                        const int row = wm * 32 + im * 16 + g4;
                        const int col = wn * 16 + in * 8 + (t4 << 1);
                        *(float2*)(gb + row * 34 + col) =
                            make_float2(acc[L][im][in][0], acc[L][im][in][1]);
                        *(float2*)(gb + (row + 8) * 34 + col) =
                            make_float2(acc[L][im][in][2], acc[L][im][in][3]);
                    }
                }
            }
        }
        __syncthreads();

        // ---- layer0 cell update ----
        if (t < SS) {
            const float* s0 = gsm + cbase * 34;
            const float* s1 = gsm + GSM_SEC + cbase * 34;
            const float gi0 = s0[u0]      + s1[u0]      + gxi.x;
            const float gi1 = s0[u0 + 1]  + s1[u0 + 1]  + gxi.y;
            const float gf0 = s0[8 + u0]  + s1[8 + u0]  + gxf.x;
            const float gf1 = s0[9 + u0]  + s1[9 + u0]  + gxf.y;
            const float gg0 = s0[16 + u0] + s1[16 + u0] + gxg.x;
            const float gg1 = s0[17 + u0] + s1[17 + u0] + gxg.y;
            const float go0 = s0[24 + u0] + s1[24 + u0] + gxo.x;
            const float go1 = s0[25 + u0] + s1[25 + u0] + gxo.y;
            const float i0 = 1.f / (1.f + expf(-gi0));
            const float i1 = 1.f / (1.f + expf(-gi1));
            const float f0 = 1.f / (1.f + expf(-gf0));
            const float f1 = 1.f / (1.f + expf(-gf1));
            const float z0 = tanhf(gg0);
            const float z1 = tanhf(gg1);
            const float o0 = 1.f / (1.f + expf(-go0));
            const float o1 = 1.f / (1.f + expf(-go1));
            c0a = f0 * c0a + i0 * z0;
            c0b = f1 * c0b + i1 * z1;
            const float h0 = o0 * tanhf(c0a);
            const float h1 = o1 * tanhf(c0b);
            h1n[cbase * (HH / 2) + ((jb + u0) >> 1)] = pack_h2(h0, h1);
        }

        // ---- layer1 cell update (computes h2[t-1]) ----
        if (t > 0) {
            const float* s2 = gsm + 2 * GSM_SEC + cbase * 34;
            const float* s3 = gsm + 3 * GSM_SEC + cbase * 34;
            const float gi0 = s2[u0]      + s3[u0]      + bs[0];
            const float gi1 = s2[u0 + 1]  + s3[u0 + 1]  + bs[1];
            const float gf0 = s2[8 + u0]  + s3[8 + u0]  + bs[2];
            const float gf1 = s2[9 + u0]  + s3[9 + u0]  + bs[3];
            const float gg0 = s2[16 + u0] + s3[16 + u0] + bs[4];
            const float gg1 = s2[17 + u0] + s3[17 + u0] + bs[5];
            const float go0 = s2[24 + u0] + s3[24 + u0] + bs[6];
            const float go1 = s2[25 + u0] + s3[25 + u0] + bs[7];
            const float i0 = 1.f / (1.f + expf(-gi0));
            const float i1 = 1.f / (1.f + expf(-gi1));
            const float f0 = 1.f / (1.f + expf(-gf0));
            const float f1 = 1.f / (1.f + expf(-gf1));
            const float z0 = tanhf(gg0);
            const float z1 = tanhf(gg1);
            const float o0 = 1.f / (1.f + expf(-go0));
            const float o1 = 1.f / (1.f + expf(-go1));
            c1a = f0 * c1a + i0 * z0;
            c1b = f1 * c1b + i1 * z1;
            const float h0 = o0 * tanhf(c1a);
            const float h1 = o1 * tanhf(c1b);
            h2n[cbase * (HH / 2) + ((jb + u0) >> 1)] = pack_h2(h0, h1);
            const float r0 = h0 > 0.f ? h0 : 0.f;
            const float r1 = h1 > 0.f ? h1 : 0.f;
            *(float2*)(out + (size_t)cbase * (SS * HH) + (size_t)(t - 1) * HH + jb + u0) =
                make_float2(1.f / (1.f + expf(-r0)), 1.f / (1.f + expf(-r1)));
        }

        grid_barrier(nct);
    }
}

// ---------------- launch ----------------
extern "C" void kernel_launch(void* const* d_in, const int* in_sizes, int n_in,
                              void* d_out, int out_size) {
    const float* x    = (const float*)d_in[0];
    const float* Wih0 = (const float*)d_in[1];
    const float* Whh0 = (const float*)d_in[2];
    const float* bih0 = (const float*)d_in[3];
    const float* bhh0 = (const float*)d_in[4];
    const float* Wih1 = (const float*)d_in[5];
    const float* Whh1 = (const float*)d_in[6];
    const float* bih1 = (const float*)d_in[7];
    const float* bhh1 = (const float*)d_in[8];
    float* out = (float*)d_out;

    float* gx0;
    cudaGetSymbolAddress((void**)&gx0, d_gx0);

    cudaFuncSetAttribute(fused_rec,
                         cudaFuncAttributeMaxDynamicSharedMemorySize, REC_SMEM_BYTES);

    dim3 gridP(G4H / 128, (BB * SS) / 64);   // (32, 256)

    proj_kernel<<<gridP, 256>>>(x, Wih0, bih0, bhh0, gx0, DD);
    fused_rec<<<128, 256, REC_SMEM_BYTES>>>(gx0, Whh0, Wih1, Whh1, bih1, bhh1, out);
}

// round 7
// speedup vs baseline: 3.9858x; 1.0002x over previous
#include <cuda_runtime.h>
#include <cuda_fp16.h>
#include <cstdint>

#define HH   1024
#define BB   64
#define SS   256
#define DD   512
#define G4H  4096

// ---------------- scratch (device globals: allocation-free) ----------------
__device__ float d_gx0[(size_t)SS * BB * G4H];   // [S,B,4H] layer0 input proj
__device__ unsigned d_h1r[2][BB * HH / 2];       // h1 ring (fp16 half2)
__device__ unsigned d_h2r[2][BB * HH / 2];       // h2 ring (fp16 half2)
__device__ unsigned g_cnt;
__device__ volatile unsigned g_gen;

// ---------------- helpers ----------------
__device__ __forceinline__ unsigned f2tf(float x) {
    unsigned r;
    asm("cvt.rna.tf32.f32 %0, %1;" : "=r"(r) : "f"(x));
    return r;
}

__device__ __forceinline__ void st4(unsigned* p, float4 v) {
    p[0] = f2tf(v.x); p[1] = f2tf(v.y); p[2] = f2tf(v.z); p[3] = f2tf(v.w);
}

__device__ __forceinline__ unsigned pack_h2(float a, float b) {
    __half2 h = __floats2half2_rn(a, b);
    return *(unsigned*)&h;
}

__device__ __forceinline__ void mma8(float d[4], const unsigned a[4], const unsigned b[2]) {
    asm volatile(
        "mma.sync.aligned.m16n8k8.row.col.f32.tf32.tf32.f32 "
        "{%0,%1,%2,%3},{%4,%5,%6,%7},{%8,%9},{%0,%1,%2,%3};\n"
        : "+f"(d[0]), "+f"(d[1]), "+f"(d[2]), "+f"(d[3])
        : "r"(a[0]), "r"(a[1]), "r"(a[2]), "r"(a[3]), "r"(b[0]), "r"(b[1]));
}

__device__ __forceinline__ void mma16h(float d[4], const unsigned a[4], const unsigned b[2]) {
    asm volatile(
        "mma.sync.aligned.m16n8k16.row.col.f32.f16.f16.f32 "
        "{%0,%1,%2,%3},{%4,%5,%6,%7},{%8,%9},{%0,%1,%2,%3};\n"
        : "+f"(d[0]), "+f"(d[1]), "+f"(d[2]), "+f"(d[3])
        : "r"(a[0]), "r"(a[1]), "r"(a[2]), "r"(a[3]), "r"(b[0]), "r"(b[1]));
}

__device__ __forceinline__ void ldsm_x4(unsigned (&r)[4], unsigned addr) {
    asm volatile(
        "ldmatrix.sync.aligned.m8n8.x4.shared.b16 {%0,%1,%2,%3}, [%4];\n"
        : "=r"(r[0]), "=r"(r[1]), "=r"(r[2]), "=r"(r[3]) : "r"(addr));
}

__device__ __forceinline__ void grid_barrier(unsigned nct) {
    __threadfence();
    __syncthreads();
    if (threadIdx.x == 0) {
        const unsigned g = g_gen;
        if (atomicAdd(&g_cnt, 1u) == nct - 1u) {
            g_cnt = 0u;
            __threadfence();
            g_gen = g + 1u;
        } else {
            while (g_gen == g) __nanosleep(20);
            __threadfence();
        }
    }
    __syncthreads();
}

// ---------------- input-projection GEMM (tf32, layer0 only) ----------------
__global__ __launch_bounds__(256) void proj_kernel(
    const float* __restrict__ A, const float* __restrict__ W,
    const float* __restrict__ bias1, const float* __restrict__ bias2,
    float* __restrict__ C, int K) {
    __shared__ unsigned As[2][64][20];
    __shared__ unsigned Bs[2][128][20];

    const int tid = threadIdx.x;
    const int lane = tid & 31, warp = tid >> 5;
    const int wm = warp >> 2, wn = warp & 3;
    const int g4 = lane >> 2, t4 = lane & 3;
    const int m0 = blockIdx.y * 64;
    const int n0 = blockIdx.x * 128;

    float acc[2][4][4];
#pragma unroll
    for (int a = 0; a < 2; a++)
#pragma unroll
        for (int b = 0; b < 4; b++)
#pragma unroll
            for (int c = 0; c < 4; c++) acc[a][b][c] = 0.f;

    const int ar = tid >> 2;
    const int ac = (tid & 3) << 2;
    const float* Ap  = A + (size_t)(m0 + ar) * K + ac;
    const float* Bp0 = W + (size_t)(n0 + ar) * K + ac;
    const float* Bp1 = W + (size_t)(n0 + ar + 64) * K + ac;
    const int KT = K >> 4;

    float4 av  = *(const float4*)Ap;
    float4 bv0 = *(const float4*)Bp0;
    float4 bv1 = *(const float4*)Bp1;
    st4(&As[0][ar][ac], av);
    st4(&Bs[0][ar][ac], bv0);
    st4(&Bs[0][ar + 64][ac], bv1);
    __syncthreads();

    int buf = 0;
    for (int kt = 0; kt < KT; kt++) {
        const int kn = (kt + 1) << 4;
        if (kt + 1 < KT) {
            av  = *(const float4*)(Ap + kn);
            bv0 = *(const float4*)(Bp0 + kn);
            bv1 = *(const float4*)(Bp1 + kn);
        }
#pragma unroll
        for (int kk = 0; kk < 2; kk++) {
            const int k8 = kk * 8;
            unsigned af[2][4], bf[4][2];
#pragma unroll
            for (int im = 0; im < 2; im++) {
                const int r = wm * 32 + im * 16;
                af[im][0] = As[buf][r + g4][k8 + t4];
                af[im][1] = As[buf][r + 8 + g4][k8 + t4];
                af[im][2] = As[buf][r + g4][k8 + 4 + t4];
                af[im][3] = As[buf][r + 8 + g4][k8 + 4 + t4];
            }
#pragma unroll
            for (int in = 0; in < 4; in++) {
                const int c = wn * 32 + in * 8;
                bf[in][0] = Bs[buf][c + g4][k8 + t4];
                bf[in][1] = Bs[buf][c + g4][k8 + 4 + t4];
            }
#pragma unroll
            for (int im = 0; im < 2; im++)
#pragma unroll
                for (int in = 0; in < 4; in++)
                    mma8(acc[im][in], af[im], bf[in]);
        }
        if (kt + 1 < KT) {
            st4(&As[buf ^ 1][ar][ac], av);
            st4(&Bs[buf ^ 1][ar][ac], bv0);
            st4(&Bs[buf ^ 1][ar + 64][ac], bv1);
        }
        __syncthreads();
        buf ^= 1;
    }

#pragma unroll
    for (int im = 0; im < 2; im++) {
#pragma unroll
        for (int in = 0; in < 4; in++) {
            const int col = n0 + wn * 32 + in * 8 + (t4 << 1);
            const float bb0 = bias1[col] + bias2[col];
            const float bb1 = bias1[col + 1] + bias2[col + 1];
            const int r0 = m0 + wm * 32 + im * 16 + g4;
            const int r1 = r0 + 8;
            // row m = b*S+s  ->  gx[(s*B+b)]
            const size_t o0 = ((size_t)((r0 & (SS - 1)) * BB + (r0 >> 8))) * G4H + col;
            const size_t o1 = ((size_t)((r1 & (SS - 1)) * BB + (r1 >> 8))) * G4H + col;
            *(float2*)(C + o0) = make_float2(acc[im][in][0] + bb0, acc[im][in][1] + bb1);
            *(float2*)(C + o1) = make_float2(acc[im][in][2] + bb0, acc[im][in][3] + bb1);
        }
    }
}

// ---------------- fused 2-layer persistent recurrent kernel (ldmatrix) ----
// 128 CTAs x 256 threads. CTA owns 8 hidden units (jb) of BOTH layers.
// Per phase t (0..256):
//   layer0: h1[t]   = cell( gx0[t] + W_hh0 @ h1[t-1] )                (t<256)
//   layer1: h2[t-1] = cell( [W_ih1;W_hh1] @ [h1[t-1]; h2[t-2]] + b )  (t>0)
// W slabs XOR-swizzled (kw ^= (n&7)<<2) at natural strides 512/1024 words.
// All fragments loaded via ldmatrix.x4 (conflict-free).
// smem (uints): Ws0[32][512] | Ws1[32][1024] | As[2][64][68] (gsm unioned)
#define WS0_STRIDE 512
#define WS1_STRIDE 1024
#define OFF_WS1   (32 * WS0_STRIDE)                 // 16384
#define OFF_AS    (OFF_WS1 + 32 * WS1_STRIDE)       // 49152
#define AS_STRIDE 68
#define AS_BUF    (64 * AS_STRIDE)                  // 4352
#define SMEM_WORDS (OFF_AS + 2 * AS_BUF)            // 57856
#define REC_SMEM_BYTES (SMEM_WORDS * 4)             // 231424 (< 231936 proven)
#define GSM_SEC   (64 * 34)                         // 2176 floats per section

// one chunk = 64 rows x 64 uints (128 fp16 k) = 16KB ; 4 x 16B per thread
__device__ __forceinline__ void prefetch_chunk(const unsigned* src0, int chunkk,
                                               unsigned* dst, int tid) {
#pragma unroll
    for (int it = 0; it < 4; it++) {
        const int s = tid + it * 256;
        const int row = s >> 4;
        const int c4 = (s & 15) << 2;
        const unsigned* src = src0 + (size_t)row * (HH / 2) + chunkk * 64 + c4;
        unsigned d = (unsigned)__cvta_generic_to_shared(dst + row * AS_STRIDE + c4);
        asm volatile("cp.async.cg.shared.global [%0], [%1], 16;\n" :: "r"(d), "l"(src));
    }
    asm volatile("cp.async.commit_group;\n");
}

__global__ __launch_bounds__(256) void fused_rec(
    const float* __restrict__ gx, const float* __restrict__ Whh0,
    const float* __restrict__ Wih1, const float* __restrict__ Whh1,
    const float* __restrict__ bih1, const float* __restrict__ bhh1,
    float* __restrict__ out) {
    extern __shared__ unsigned smu[];
    unsigned* Ws0 = smu;
    unsigned* Ws1 = smu + OFF_WS1;
    unsigned* Asm = smu + OFF_AS;
    float* gsm = (float*)(smu + OFF_AS);   // union: valid after GEMM of a phase

    const int tid = threadIdx.x;
    const int lane = tid & 31, warp = tid >> 5;
    const int wk = warp >> 2;            // K-split half
    const int wm = (warp >> 1) & 1;      // M half (32 rows)
    const int wn = warp & 1;             // N half (16 cols)
    const int jb = blockIdx.x << 3;      // 8 hidden units per CTA
    const unsigned nct = gridDim.x;

    // --- one-time init: W slabs (fp16, swizzled), zero rings, biases ---
    for (int idx = tid; idx < 32 * 512; idx += 256) {
        const int v = idx >> 9, kh = idx & 511;
        const int grow = (v >> 3) * HH + jb + (v & 7);
        const float2 w2 = *(const float2*)(Whh0 + (size_t)grow * HH + 2 * kh);
        Ws0[v * WS0_STRIDE + (kh ^ ((v & 7) << 2))] = pack_h2(w2.x, w2.y);
    }
    for (int idx = tid; idx < 32 * 1024; idx += 256) {
        const int v = idx >> 10, kh = idx & 1023;
        const int grow = (v >> 3) * HH + jb + (v & 7);
        float2 w2;
        if (kh < 512) w2 = *(const float2*)(Wih1 + (size_t)grow * HH + 2 * kh);
        else          w2 = *(const float2*)(Whh1 + (size_t)grow * HH + 2 * (kh - 512));
        Ws1[v * WS1_STRIDE + (kh ^ ((v & 7) << 2))] = pack_h2(w2.x, w2.y);
    }
    {
        const int b = tid >> 2, q = tid & 3;
        d_h1r[0][b * (HH / 2) + (jb >> 1) + q] = 0u;
        d_h1r[1][b * (HH / 2) + (jb >> 1) + q] = 0u;
        d_h2r[0][b * (HH / 2) + (jb >> 1) + q] = 0u;
        d_h2r[1][b * (HH / 2) + (jb >> 1) + q] = 0u;
    }

    const int cbase = tid >> 2;          // batch handled in cell update
    const int u0 = (tid & 3) << 1;       // unit pair

    float bs[8];                          // layer1 per-gate biases
#pragma unroll
    for (int g = 0; g < 4; g++) {
        bs[2 * g]     = bih1[g * HH + jb + u0]     + bhh1[g * HH + jb + u0];
        bs[2 * g + 1] = bih1[g * HH + jb + u0 + 1] + bhh1[g * HH + jb + u0 + 1];
    }

    // --- lane-constant ldmatrix addressing ---
    const unsigned base_u = (unsigned)__cvta_generic_to_shared(smu);
    const int r8   = lane & 7;
    const int sel8 = (lane & 8) ? 8 : 0;      // +8 rows for matrices 1,3
    const int selk = (lane & 16) ? 4 : 0;     // +8 fp16 k for matrices 2,3
    const int szB  = selk ^ (r8 << 2);        // swizzled k-offset part for B
    const unsigned offA0 = (unsigned)((wm * 32 + r8 + sel8) * AS_STRIDE + selk);
    const unsigned offA1 = offA0 + 16 * AS_STRIDE;
    const unsigned abase[2] = { base_u + OFF_AS * 4,
                                base_u + (OFF_AS + AS_BUF) * 4 };
    const unsigned b1base = base_u + (OFF_WS1 + (wn * 16 + r8 + sel8) * WS1_STRIDE) * 4;
    const unsigned b0base = base_u + ((wn * 16 + r8 + sel8) * WS0_STRIDE) * 4;

    float c0a = 0.f, c0b = 0.f;          // layer0 cell state (this thread's pair)
    float c1a = 0.f, c1b = 0.f;          // layer1 cell state

    grid_barrier(nct);

#pragma unroll 1
    for (int t = 0; t <= SS; t++) {
        const unsigned* h1p = d_h1r[(t + 1) & 1];   // h1[t-1]
        unsigned* h1n = d_h1r[t & 1];               // h1[t]
        const unsigned* h2p = d_h2r[t & 1];         // h2[t-2]
        unsigned* h2n = d_h2r[(t + 1) & 1];         // h2[t-1]

        // hoist gx0[t] (lands during GEMM)
        float2 gxi, gxf, gxg, gxo;
        if (t < SS) {
            const float* gp = gx + (size_t)t * (BB * G4H) + (size_t)cbase * G4H + jb + u0;
            gxi = *(const float2*)(gp);
            gxf = *(const float2*)(gp + HH);
            gxg = *(const float2*)(gp + 2 * HH);
            gxo = *(const float2*)(gp + 3 * HH);
        }

        float acc[2][2][2][4];   // [layer][im][in][4]
#pragma unroll
        for (int L = 0; L < 2; L++)
#pragma unroll
            for (int a = 0; a < 2; a++)
#pragma unroll
                for (int b = 0; b < 2; b++)
#pragma unroll
                    for (int c = 0; c < 4; c++) acc[L][a][b][c] = 0.f;

        prefetch_chunk(h1p, 0, Asm, tid);
        prefetch_chunk(h1p, 1, Asm + AS_BUF, tid);

#pragma unroll 1
        for (int c = 0; c < 16; c++) {
            if (c < 15) { asm volatile("cp.async.wait_group 1;\n"); }
            else        { asm volatile("cp.async.wait_group 0;\n"); }
            __syncthreads();
            const unsigned ab = abase[c & 1];
            const int kwarp = c * 64 + wk * 32;
#pragma unroll
            for (int kk = 0; kk < 4; kk++) {
                const int ks = wk * 32 + kk * 8;
                const int kw = kwarp + kk * 8;
                unsigned af0[4], af1[4];
                ldsm_x4(af0, ab + ((offA0 + ks) << 2));
                ldsm_x4(af1, ab + ((offA1 + ks) << 2));
                // layer1 (always)
                {
                    unsigned bq[4];
                    ldsm_x4(bq, b1base + ((unsigned)(kw ^ szB) << 2));
                    unsigned bfa[2] = { bq[0], bq[2] };
                    unsigned bfb[2] = { bq[1], bq[3] };
                    mma16h(acc[1][0][0], af0, bfa);
                    mma16h(acc[1][0][1], af0, bfb);
                    mma16h(acc[1][1][0], af1, bfa);
                    mma16h(acc[1][1][1], af1, bfb);
                }
                // layer0 (chunks 0-7 only)
                if (c < 8) {
                    unsigned bq[4];
                    ldsm_x4(bq, b0base + ((unsigned)(kw ^ szB) << 2));
                    unsigned bfa[2] = { bq[0], bq[2] };
                    unsigned bfb[2] = { bq[1], bq[3] };
                    mma16h(acc[0][0][0], af0, bfa);
                    mma16h(acc[0][0][1], af0, bfb);
                    mma16h(acc[0][1][0], af1, bfa);
                    mma16h(acc[0][1][1], af1, bfb);
                }
            }
            __syncthreads();
            if (c + 2 < 16) {
                const int nc = c + 2;
                prefetch_chunk(nc < 8 ? h1p : h2p, nc & 7, Asm + (c & 1) * AS_BUF, tid);
            }
        }

        // dump partials into gsm (unioned over As): section = layer*2 + wk
        {
            const int g4 = lane >> 2, t4 = lane & 3;
#pragma unroll
            for (int L = 0; L < 2; L++) {
                float* gb = gsm + (L * 2 + wk) * GSM_SEC;
#pragma unroll
                for (int im = 0; im < 2; im++) {
#pragma unroll
                    for (int in = 0; in < 2; in++) {
                        const int row = wm * 32 + im * 16 + g4;
                        const int col = wn * 16 + in * 8 + (t4 << 1);
                        *(float2*)(gb + row * 34 + col) =
                            make_float2(acc[L][im][in][0], acc[L][im][in][1]);
                        *(float2*)(gb + (row + 8) * 34 + col) =
                            make_float2(acc[L][im][in][2], acc[L][im][in][3]);
                    }
                }
            }
        }
        __syncthreads();

        // ---- layer0 cell update ----
        if (t < SS) {
            const float* s0 = gsm + cbase * 34;
            const float* s1 = gsm + GSM_SEC + cbase * 34;
            const float gi0 = s0[u0]      + s1[u0]      + gxi.x;
            const float gi1 = s0[u0 + 1]  + s1[u0 + 1]  + gxi.y;
            const float gf0 = s0[8 + u0]  + s1[8 + u0]  + gxf.x;
            const float gf1 = s0[9 + u0]  + s1[9 + u0]  + gxf.y;
            const float gg0 = s0[16 + u0] + s1[16 + u0] + gxg.x;
            const float gg1 = s0[17 + u0] + s1[17 + u0] + gxg.y;
            const float go0 = s0[24 + u0] + s1[24 + u0] + gxo.x;
            const float go1 = s0[25 + u0] + s1[25 + u0] + gxo.y;
            const float i0 = 1.f / (1.f + expf(-gi0));
            const float i1 = 1.f / (1.f + expf(-gi1));
            const float f0 = 1.f / (1.f + expf(-gf0));
            const float f1 = 1.f / (1.f + expf(-gf1));
            const float z0 = tanhf(gg0);
            const float z1 = tanhf(gg1);
            const float o0 = 1.f / (1.f + expf(-go0));
            const float o1 = 1.f / (1.f + expf(-go1));
            c0a = f0 * c0a + i0 * z0;
            c0b = f1 * c0b + i1 * z1;
            const float h0 = o0 * tanhf(c0a);
            const float h1 = o1 * tanhf(c0b);
            h1n[cbase * (HH / 2) + ((jb + u0) >> 1)] = pack_h2(h0, h1);
        }

        // ---- layer1 cell update (computes h2[t-1]) ----
        if (t > 0) {
            const float* s2 = gsm + 2 * GSM_SEC + cbase * 34;
            const float* s3 = gsm + 3 * GSM_SEC + cbase * 34;
            const float gi0 = s2[u0]      + s3[u0]      + bs[0];
            const float gi1 = s2[u0 + 1]  + s3[u0 + 1]  + bs[1];
            const float gf0 = s2[8 + u0]  + s3[8 + u0]  + bs[2];
            const float gf1 = s2[9 + u0]  + s3[9 + u0]  + bs[3];
            const float gg0 = s2[16 + u0] + s3[16 + u0] + bs[4];
            const float gg1 = s2[17 + u0] + s3[17 + u0] + bs[5];
            const float go0 = s2[24 + u0] + s3[24 + u0] + bs[6];
            const float go1 = s2[25 + u0] + s3[25 + u0] + bs[7];
            const float i0 = 1.f / (1.f + expf(-gi0));
            const float i1 = 1.f / (1.f + expf(-gi1));
            const float f0 = 1.f / (1.f + expf(-gf0));
            const float f1 = 1.f / (1.f + expf(-gf1));
            const float z0 = tanhf(gg0);
            const float z1 = tanhf(gg1);
            const float o0 = 1.f / (1.f + expf(-go0));
            const float o1 = 1.f / (1.f + expf(-go1));
            c1a = f0 * c1a + i0 * z0;
            c1b = f1 * c1b + i1 * z1;
            const float h0 = o0 * tanhf(c1a);
            const float h1 = o1 * tanhf(c1b);
            h2n[cbase * (HH / 2) + ((jb + u0) >> 1)] = pack_h2(h0, h1);
            const float r0 = h0 > 0.f ? h0 : 0.f;
            const float r1 = h1 > 0.f ? h1 : 0.f;
            *(float2*)(out + (size_t)cbase * (SS * HH) + (size_t)(t - 1) * HH + jb + u0) =
                make_float2(1.f / (1.f + expf(-r0)), 1.f / (1.f + expf(-r1)));
        }

        grid_barrier(nct);
    }
}

// ---------------- launch ----------------
extern "C" void kernel_launch(void* const* d_in, const int* in_sizes, int n_in,
                              void* d_out, int out_size) {
    const float* x    = (const float*)d_in[0];
    const float* Wih0 = (const float*)d_in[1];
    const float* Whh0 = (const float*)d_in[2];
    const float* bih0 = (const float*)d_in[3];
    const float* bhh0 = (const float*)d_in[4];
    const float* Wih1 = (const float*)d_in[5];
    const float* Whh1 = (const float*)d_in[6];
    const float* bih1 = (const float*)d_in[7];
    const float* bhh1 = (const float*)d_in[8];
    float* out = (float*)d_out;

    float* gx0;
    cudaGetSymbolAddress((void**)&gx0, d_gx0);

    cudaFuncSetAttribute(fused_rec,
                         cudaFuncAttributeMaxDynamicSharedMemorySize, REC_SMEM_BYTES);

    dim3 gridP(G4H / 128, (BB * SS) / 64);   // (32, 256)

    proj_kernel<<<gridP, 256>>>(x, Wih0, bih0, bhh0, gx0, DD);
    fused_rec<<<128, 256, REC_SMEM_BYTES>>>(gx0, Whh0, Wih1, Whh1, bih1, bhh1, out);
}